// round 15
// baseline (speedup 1.0000x reference)
#include <cuda_runtime.h>
#include <cuda_bf16.h>
#include <math.h>
#include <cstdint>

// Problem constants
#define BB 4
#define NN 1024
#define DD 1024
#define HH 16
#define DHH 64
#define INNERC 1024          // HH*DHH
#define QKVC 3072            // 3*INNERC
#define MM 4096              // BB*NN
#define BHC 64               // BB*HH
#define NSM 148

// ---------------------------------------------------------------------------
// Scratch (__device__ globals; no allocation allowed)
// ---------------------------------------------------------------------------
__device__ __nv_bfloat16 g_xhi[(size_t)MM * DD];
__device__ __nv_bfloat16 g_xlo[(size_t)MM * DD];
__device__ __nv_bfloat16 g_wqkvThi[(size_t)QKVC * DD];
__device__ __nv_bfloat16 g_wqkvTlo[(size_t)QKVC * DD];
__device__ float g_woT[(size_t)INNERC * INNERC];        // w_out^T, tf32-rounded

// q/k in [B,H,N,DH] bf16 hi/lo (q pre-scaled by 0.125)
__device__ __nv_bfloat16 g_qhi[(size_t)BHC * NN * DHH];
__device__ __nv_bfloat16 g_qlo[(size_t)BHC * NN * DHH];
__device__ __nv_bfloat16 g_khi[(size_t)BHC * NN * DHH];
__device__ __nv_bfloat16 g_klo[(size_t)BHC * NN * DHH];
// v stored directly transposed: [B,H,DH,N]
__device__ __nv_bfloat16 g_vThi[(size_t)BHC * DHH * NN];
__device__ __nv_bfloat16 g_vTlo[(size_t)BHC * DHH * NN];
// attention output fp32 (tf32-rounded), [B*N, INNER]
__device__ float g_ao[(size_t)MM * INNERC];

// ---------------------------------------------------------------------------
// PTX helpers (sm_80-compatible; compile on plain compute_103)
// ---------------------------------------------------------------------------
__device__ __forceinline__ uint32_t smem_u32(const void* p) {
    uint32_t a;
    asm("{ .reg .u64 t; cvta.to.shared.u64 t, %1; cvt.u32.u64 %0, t; }"
        : "=r"(a) : "l"(p));
    return a;
}
#define LDSM4(r, addr) \
    asm volatile("ldmatrix.sync.aligned.m8n8.x4.shared.b16 {%0,%1,%2,%3}, [%4];" \
        : "=r"((r)[0]), "=r"((r)[1]), "=r"((r)[2]), "=r"((r)[3]) : "r"(addr))
#define MMA_BF16(d, a, b) \
    asm volatile("mma.sync.aligned.m16n8k16.row.col.f32.bf16.bf16.f32 " \
        "{%0,%1,%2,%3}, {%4,%5,%6,%7}, {%8,%9}, {%0,%1,%2,%3};" \
        : "+f"((d)[0]), "+f"((d)[1]), "+f"((d)[2]), "+f"((d)[3]) \
        : "r"((a)[0]), "r"((a)[1]), "r"((a)[2]), "r"((a)[3]), \
          "r"((b)[0]), "r"((b)[1]))
#define MMA_TF32(d, a, b) \
    asm volatile("mma.sync.aligned.m16n8k8.row.col.f32.tf32.tf32.f32 " \
        "{%0,%1,%2,%3}, {%4,%5,%6,%7}, {%8,%9}, {%0,%1,%2,%3};" \
        : "+f"((d)[0]), "+f"((d)[1]), "+f"((d)[2]), "+f"((d)[3]) \
        : "r"((a)[0]), "r"((a)[1]), "r"((a)[2]), "r"((a)[3]), \
          "r"((b)[0]), "r"((b)[1]))
#define CP16(saddr, g) \
    asm volatile("cp.async.cg.shared.global [%0], [%1], 16;" :: "r"(saddr), "l"(g))
#define CP_COMMIT() asm volatile("cp.async.commit_group;" ::: "memory")
#define CP_WAIT0()  asm volatile("cp.async.wait_group 0;" ::: "memory")

__device__ __forceinline__ float tf32rna(float x) {
    uint32_t r;
    asm("cvt.rna.tf32.f32 %0, %1;" : "=r"(r) : "f"(x));
    return __uint_as_float(r);
}
__device__ __forceinline__ void store_hilo2(
    __nv_bfloat16* hb, __nv_bfloat16* lb, size_t idx, float a, float b)
{
    __nv_bfloat16 h0 = __float2bfloat16(a);
    __nv_bfloat16 h1 = __float2bfloat16(b);
    *(__nv_bfloat162*)(hb + idx) = __nv_bfloat162(h0, h1);
    *(__nv_bfloat162*)(lb + idx) =
        __nv_bfloat162(__float2bfloat16(a - __bfloat162float(h0)),
                       __float2bfloat16(b - __bfloat162float(h1)));
}
__device__ __forceinline__ void store_hilo1(
    __nv_bfloat16* hb, __nv_bfloat16* lb, size_t idx, float a)
{
    __nv_bfloat16 h0 = __float2bfloat16(a);
    hb[idx] = h0;
    lb[idx] = __float2bfloat16(a - __bfloat162float(h0));
}
__device__ __forceinline__ void cvt_hilo(float a, float b, uint32_t& h, uint32_t& l)
{
    __nv_bfloat16 ha = __float2bfloat16(a);
    __nv_bfloat16 hbb = __float2bfloat16(b);
    __nv_bfloat162 hp(ha, hbb);
    h = *(uint32_t*)&hp;
    __nv_bfloat162 lp(__float2bfloat16(a - __bfloat162float(ha)),
                      __float2bfloat16(b - __bfloat162float(hbb)));
    l = *(uint32_t*)&lp;
}

// ---------------------------------------------------------------------------
// prep kernels
// ---------------------------------------------------------------------------
__global__ void __launch_bounds__(256) split_kernel(
    const float* __restrict__ in, __nv_bfloat16* __restrict__ hi,
    __nv_bfloat16* __restrict__ lo, int n4)
{
    int i = blockIdx.x * 256 + threadIdx.x;
    if (i >= n4) return;
    float4 v = *(const float4*)(in + i * 4);
    store_hilo2(hi, lo, (size_t)i * 4, v.x, v.y);
    store_hilo2(hi, lo, (size_t)i * 4 + 2, v.z, v.w);
}

__global__ void __launch_bounds__(256) splitT_kernel(
    const float* __restrict__ in, __nv_bfloat16* __restrict__ hiT,
    __nv_bfloat16* __restrict__ loT, int R, int C)
{
    __shared__ float t[32][33];
    const int c = blockIdx.x * 32 + threadIdx.x;
#pragma unroll
    for (int j = 0; j < 4; ++j) {
        int r = blockIdx.y * 32 + threadIdx.y + j * 8;
        t[threadIdx.y + j * 8][threadIdx.x] = in[(size_t)r * C + c];
    }
    __syncthreads();
    const int rr = blockIdx.y * 32 + threadIdx.x;
#pragma unroll
    for (int j = 0; j < 4; ++j) {
        int cc = blockIdx.x * 32 + threadIdx.y + j * 8;
        float v = t[threadIdx.x][threadIdx.y + j * 8];
        __nv_bfloat16 h = __float2bfloat16(v);
        hiT[(size_t)cc * R + rr] = h;
        loT[(size_t)cc * R + rr] = __float2bfloat16(v - __bfloat162float(h));
    }
}

// transpose + tf32 RNA rounding (for w_out)
__global__ void __launch_bounds__(256) transT_rna(
    const float* __restrict__ in, float* __restrict__ outT, int R, int C)
{
    __shared__ float t[32][33];
    const int c = blockIdx.x * 32 + threadIdx.x;
#pragma unroll
    for (int j = 0; j < 4; ++j) {
        int r = blockIdx.y * 32 + threadIdx.y + j * 8;
        t[threadIdx.y + j * 8][threadIdx.x] = in[(size_t)r * C + c];
    }
    __syncthreads();
    const int rr = blockIdx.y * 32 + threadIdx.x;
#pragma unroll
    for (int j = 0; j < 4; ++j) {
        int cc = blockIdx.x * 32 + threadIdx.y + j * 8;
        outT[(size_t)cc * R + rr] = tf32rna(t[threadIdx.x][threadIdx.y + j * 8]);
    }
}

// ---------------------------------------------------------------------------
// qkv GEMM: BK=64 (stride 72, flash-proven), 16 warps 32x32, 2-stage,
// persistent. Epilogue: q(*0.125)/k hi/lo [B,H,N,DH]; v transposed.
// ---------------------------------------------------------------------------
#define QSTR 72
#define QTILEB (128 * QSTR * 2)             // 18432
#define QSTAGEB (4 * QTILEB)                // 73728
#define QKV_SMEM_BYTES (2 * QSTAGEB)        // 147456

__global__ void __launch_bounds__(512, 1) gemm_qkv(
    const __nv_bfloat16* __restrict__ Ahi, const __nv_bfloat16* __restrict__ Alo,
    const __nv_bfloat16* __restrict__ Bthi, const __nv_bfloat16* __restrict__ Btlo,
    __nv_bfloat16* __restrict__ qhi, __nv_bfloat16* __restrict__ qlo,
    __nv_bfloat16* __restrict__ khi, __nv_bfloat16* __restrict__ klo,
    __nv_bfloat16* __restrict__ vThi, __nv_bfloat16* __restrict__ vTlo)
{
    extern __shared__ char smem[];
    const uint32_t smb = smem_u32(smem);
    const int tid = threadIdx.x;
    const int lane = tid & 31;
    const int wid = tid >> 5;
    const int mw = wid >> 2;
    const int nw = wid & 3;
    const int K = DD;
    const int NT = (QKVC >> 7) * (MM >> 7);   // 768

    const int grow = tid >> 2;                // 0..127
    const int gcol = (tid & 3) << 4;          // 0,16,32,48 elems
    const uint32_t stb = (uint32_t)(grow * QSTR + gcol) * 2;

    uint32_t aoff[2];
#pragma unroll
    for (int mt = 0; mt < 2; ++mt)
        aoff[mt] = (uint32_t)((mw * 32 + mt * 16 + (lane & 15)) * QSTR
                              + ((lane >> 4) << 3)) * 2;
    const int brow = nw * 32 + (lane & 7) + ((lane >> 4) << 3);
    const int bcol = ((lane >> 3) & 1) << 3;
    uint32_t boff[2];
    boff[0] = (uint32_t)(brow * QSTR + bcol) * 2;
    boff[1] = (uint32_t)((brow + 16) * QSTR + bcol) * 2;

    const int nst = K >> 6;   // 16

    for (int tile = blockIdx.x; tile < NT; tile += NSM) {
        const int m0 = (tile / 24) << 7;
        const int n0 = (tile % 24) << 7;
        const __nv_bfloat16* gAh = Ahi  + (size_t)(m0 + grow) * K + gcol;
        const __nv_bfloat16* gAl = Alo  + (size_t)(m0 + grow) * K + gcol;
        const __nv_bfloat16* gBh = Bthi + (size_t)(n0 + grow) * K + gcol;
        const __nv_bfloat16* gBl = Btlo + (size_t)(n0 + grow) * K + gcol;

        float acc[2][4][4];
#pragma unroll
        for (int i = 0; i < 2; ++i)
#pragma unroll
            for (int j = 0; j < 4; ++j)
#pragma unroll
                for (int k = 0; k < 4; ++k) acc[i][j][k] = 0.f;

        {
            const uint32_t d = smb + stb;
            CP16(d,                gAh); CP16(d + 16,                gAh + 8);
            CP16(d + QTILEB,       gAl); CP16(d + QTILEB + 16,       gAl + 8);
            CP16(d + 2 * QTILEB,   gBh); CP16(d + 2 * QTILEB + 16,   gBh + 8);
            CP16(d + 3 * QTILEB,   gBl); CP16(d + 3 * QTILEB + 16,   gBl + 8);
            CP_COMMIT(); CP_WAIT0();
        }
        __syncthreads();

        for (int s = 0; s < nst; ++s) {
            if (s + 1 < nst) {
                const int k0 = (s + 1) << 6;
                const uint32_t d = smb + ((s + 1) & 1) * QSTAGEB + stb;
                CP16(d,              gAh + k0); CP16(d + 16,              gAh + k0 + 8);
                CP16(d + QTILEB,     gAl + k0); CP16(d + QTILEB + 16,     gAl + k0 + 8);
                CP16(d + 2 * QTILEB, gBh + k0); CP16(d + 2 * QTILEB + 16, gBh + k0 + 8);
                CP16(d + 3 * QTILEB, gBl + k0); CP16(d + 3 * QTILEB + 16, gBl + k0 + 8);
                CP_COMMIT();
            }
            const uint32_t sb = smb + (s & 1) * QSTAGEB;
#pragma unroll
            for (int kk = 0; kk < 4; ++kk) {
                const uint32_t kb = kk * 32;
                uint32_t ah[2][4], al[2][4], bh[4][2], bl[4][2];
#pragma unroll
                for (int mt = 0; mt < 2; ++mt) {
                    LDSM4(ah[mt], sb + aoff[mt] + kb);
                    LDSM4(al[mt], sb + QTILEB + aoff[mt] + kb);
                }
#pragma unroll
                for (int p = 0; p < 2; ++p) {
                    uint32_t t4[4];
                    LDSM4(t4, sb + 2 * QTILEB + boff[p] + kb);
                    bh[2 * p][0] = t4[0]; bh[2 * p][1] = t4[1];
                    bh[2 * p + 1][0] = t4[2]; bh[2 * p + 1][1] = t4[3];
                    LDSM4(t4, sb + 3 * QTILEB + boff[p] + kb);
                    bl[2 * p][0] = t4[0]; bl[2 * p][1] = t4[1];
                    bl[2 * p + 1][0] = t4[2]; bl[2 * p + 1][1] = t4[3];
                }
#pragma unroll
                for (int mt = 0; mt < 2; ++mt)
#pragma unroll
                    for (int nt = 0; nt < 4; ++nt)
                        MMA_BF16(acc[mt][nt], ah[mt], bh[nt]);
#pragma unroll
                for (int mt = 0; mt < 2; ++mt)
#pragma unroll
                    for (int nt = 0; nt < 4; ++nt)
                        MMA_BF16(acc[mt][nt], ah[mt], bl[nt]);
#pragma unroll
                for (int mt = 0; mt < 2; ++mt)
#pragma unroll
                    for (int nt = 0; nt < 4; ++nt)
                        MMA_BF16(acc[mt][nt], al[mt], bh[nt]);
            }
            CP_WAIT0();
            __syncthreads();
        }

        // epilogue: q (*0.125) / k in [B,H,N,DH]; v transposed into [B,H,DH,N]
#pragma unroll
        for (int nt = 0; nt < 4; ++nt) {
            const int cc = n0 + nw * 32 + nt * 8 + ((lane & 3) << 1);
            const int sec = cc >> 10;
            const int h = (cc & 1023) >> 6;
            const int d = cc & 63;
#pragma unroll
            for (int mt = 0; mt < 2; ++mt) {
                const int r0 = m0 + mw * 32 + mt * 16 + (lane >> 2);
                const int b = r0 >> 10;
                const int n = r0 & 1023;
                const size_t bhbase = ((size_t)b * HH + h);
                if (sec == 0) {
                    store_hilo2(qhi, qlo, (bhbase * NN + n) * DHH + d,
                                acc[mt][nt][0] * 0.125f, acc[mt][nt][1] * 0.125f);
                    store_hilo2(qhi, qlo, (bhbase * NN + n + 8) * DHH + d,
                                acc[mt][nt][2] * 0.125f, acc[mt][nt][3] * 0.125f);
                } else if (sec == 1) {
                    store_hilo2(khi, klo, (bhbase * NN + n) * DHH + d,
                                acc[mt][nt][0], acc[mt][nt][1]);
                    store_hilo2(khi, klo, (bhbase * NN + n + 8) * DHH + d,
                                acc[mt][nt][2], acc[mt][nt][3]);
                } else {
                    const size_t vb = bhbase * DHH;
                    store_hilo1(vThi, vTlo, (vb + d) * NN + n,         acc[mt][nt][0]);
                    store_hilo1(vThi, vTlo, (vb + d + 1) * NN + n,     acc[mt][nt][1]);
                    store_hilo1(vThi, vTlo, (vb + d) * NN + n + 8,     acc[mt][nt][2]);
                    store_hilo1(vThi, vTlo, (vb + d + 1) * NN + n + 8, acc[mt][nt][3]);
                }
            }
        }
    }
}

// ---------------------------------------------------------------------------
// tf32 out-projection GEMM: out = ao @ woT^T + bias (unchanged from round 14)
// ---------------------------------------------------------------------------
#define TFSTR 36
#define TFTILEB (128 * TFSTR * 4)           // 18432
#define TFSTAGEB (2 * TFTILEB)              // 36864
#define TF_SMEM_BYTES (2 * TFSTAGEB)        // 73728

__global__ void __launch_bounds__(512, 1) gemm_out_tf32(
    const float* __restrict__ A, const float* __restrict__ Bt,
    const float* __restrict__ bias, float* __restrict__ C)
{
    extern __shared__ char smem[];
    const uint32_t smb = smem_u32(smem);
    const int tid = threadIdx.x;
    const int lane = tid & 31;
    const int wid = tid >> 5;
    const int mw = wid >> 2;
    const int nw = wid & 3;
    const int NT = (MM >> 7) * (INNERC >> 7);   // 256

    const int grow = tid >> 2;
    const int gcolf = (tid & 3) << 3;
    const uint32_t stb = (uint32_t)(grow * TFSTR + gcolf) * 4;

    const int mat = lane >> 3;
    const int rr = lane & 7;
    uint32_t aoff[2];
#pragma unroll
    for (int mt = 0; mt < 2; ++mt)
        aoff[mt] = (uint32_t)((mw * 32 + mt * 16 + ((mat & 1) << 3) + rr) * TFSTR
                              + ((mat >> 1) << 2)) * 4;
    uint32_t boff[2];
#pragma unroll
    for (int p = 0; p < 2; ++p)
        boff[p] = (uint32_t)((nw * 32 + p * 16 + ((mat >> 1) << 3) + rr) * TFSTR
                             + ((mat & 1) << 2)) * 4;

    const int nst = INNERC >> 5;   // 32

    for (int tile = blockIdx.x; tile < NT; tile += NSM) {
        const int m0 = (tile >> 3) << 7;
        const int n0 = (tile & 7) << 7;
        const float* gA = A  + (size_t)(m0 + grow) * INNERC + gcolf;
        const float* gB = Bt + (size_t)(n0 + grow) * INNERC + gcolf;

        float acc[2][4][4];
#pragma unroll
        for (int i = 0; i < 2; ++i)
#pragma unroll
            for (int j = 0; j < 4; ++j)
#pragma unroll
                for (int k = 0; k < 4; ++k) acc[i][j][k] = 0.f;

        {
            const uint32_t d = smb + stb;
            CP16(d,      gA); CP16(d + 16,      gA + 4);
            CP16(d + TFTILEB, gB); CP16(d + TFTILEB + 16, gB + 4);
            CP_COMMIT(); CP_WAIT0();
        }
        __syncthreads();

        for (int s = 0; s < nst; ++s) {
            if (s + 1 < nst) {
                const int k0 = (s + 1) << 5;
                const uint32_t d = smb + ((s + 1) & 1) * TFSTAGEB + stb;
                CP16(d,      gA + k0); CP16(d + 16,      gA + k0 + 4);
                CP16(d + TFTILEB, gB + k0); CP16(d + TFTILEB + 16, gB + k0 + 4);
                CP_COMMIT();
            }
            const uint32_t sb = smb + (s & 1) * TFSTAGEB;
#pragma unroll
            for (int kc = 0; kc < 4; ++kc) {
                const uint32_t kb = kc * 32;
                uint32_t af[2][4], bf[4][2];
#pragma unroll
                for (int mt = 0; mt < 2; ++mt)
                    LDSM4(af[mt], sb + aoff[mt] + kb);
#pragma unroll
                for (int p = 0; p < 2; ++p) {
                    uint32_t t4[4];
                    LDSM4(t4, sb + TFTILEB + boff[p] + kb);
                    bf[2 * p][0] = t4[0]; bf[2 * p][1] = t4[1];
                    bf[2 * p + 1][0] = t4[2]; bf[2 * p + 1][1] = t4[3];
                }
#pragma unroll
                for (int mt = 0; mt < 2; ++mt)
#pragma unroll
                    for (int nt = 0; nt < 4; ++nt)
                        MMA_TF32(acc[mt][nt], af[mt], bf[nt]);
            }
            CP_WAIT0();
            __syncthreads();
        }

#pragma unroll
        for (int mt = 0; mt < 2; ++mt) {
            const int r0 = m0 + mw * 32 + mt * 16 + (lane >> 2);
#pragma unroll
            for (int nt = 0; nt < 4; ++nt) {
                const int cc = n0 + nw * 32 + nt * 8 + ((lane & 3) << 1);
                float2 bv = *(const float2*)(bias + cc);
                float2 v0 = make_float2(acc[mt][nt][0] + bv.x, acc[mt][nt][1] + bv.y);
                float2 v1 = make_float2(acc[mt][nt][2] + bv.x, acc[mt][nt][3] + bv.y);
                *(float2*)(C + (size_t)r0 * INNERC + cc) = v0;
                *(float2*)(C + (size_t)(r0 + 8) * INNERC + cc) = v1;
            }
        }
    }
}

// ---------------------------------------------------------------------------
// flash_tc: fused masked attention, 256 threads (proven round-13 structure),
// persistent; epilogue writes fp32 (tf32-rounded) ao.
// ---------------------------------------------------------------------------
#define FQSTR 72
#define FQTILE 18432                      // 128*72*2
#define FVSTR 136
#define FVTILE 17408                      // 64*136*2
#define F_MASK 0
#define F_QHI 4096
#define F_QLO (F_QHI + FQTILE)
#define F_K(st) (40960 + (st) * 2 * FQTILE)
#define F_V(st) (114688 + (st) * 2 * FVTILE)
#define FLASH_SMEM 184320

__global__ void __launch_bounds__(256, 1) flash_tc(
    const __nv_bfloat16* __restrict__ qhi, const __nv_bfloat16* __restrict__ qlo,
    const __nv_bfloat16* __restrict__ khi, const __nv_bfloat16* __restrict__ klo,
    const __nv_bfloat16* __restrict__ vThi, const __nv_bfloat16* __restrict__ vTlo,
    const float* __restrict__ mask, float* __restrict__ ao)
{
    extern __shared__ char smem[];
    const uint32_t smb = smem_u32(smem);
    const int tid = threadIdx.x;
    const int lane = tid & 31;
    const int wid = tid >> 5;
    const int rw = wid * 16;
    const int rloc = lane >> 2;

    const uint32_t bkbase = (uint32_t)(((lane & 7) + ((lane >> 4) << 3)) * FQSTR
                                       + (((lane >> 3) & 1) << 3)) * 2;
    const uint32_t bvbase = (uint32_t)(((lane & 7) + ((lane >> 4) << 3)) * FVSTR
                                       + (((lane >> 3) & 1) << 3)) * 2;
    const uint32_t aQ = (uint32_t)((rw + (lane & 15)) * FQSTR + ((lane >> 4) << 3)) * 2;
    const float* smask = (const float*)smem;

    for (int tile = blockIdx.x; tile < 512; tile += NSM) {
        const int bh = tile >> 3;
        const int i0 = (tile & 7) << 7;
        const int b = bh >> 4;
        const int h = bh & 15;
        const size_t hb = (size_t)bh * NN * DHH;
        const __nv_bfloat16* kH = khi + hb;
        const __nv_bfloat16* kL = klo + hb;
        const __nv_bfloat16* vH = vThi + (size_t)bh * DHH * NN;
        const __nv_bfloat16* vL = vTlo + (size_t)bh * DHH * NN;

        // ---- prologue: mask + Q + K0 + V0 via cp.async
        CP16(smb + F_MASK + tid * 16, mask + b * NN + tid * 4);
#pragma unroll
        for (int t = 0; t < 4; ++t) {
            const int idx = tid + t * 256;
            const int row = idx >> 3;
            const int col = (idx & 7) << 3;
            const uint32_t so = (uint32_t)(row * FQSTR + col) * 2;
            CP16(smb + F_QHI + so, qhi + hb + (size_t)(i0 + row) * DHH + col);
            CP16(smb + F_QLO + so, qlo + hb + (size_t)(i0 + row) * DHH + col);
            CP16(smb + F_K(0) + so,          kH + (size_t)row * DHH + col);
            CP16(smb + F_K(0) + FQTILE + so, kL + (size_t)row * DHH + col);
        }
#pragma unroll
        for (int t = 0; t < 4; ++t) {
            const int idx = tid + t * 256;
            const int vr = idx >> 4;
            const int vc = (idx & 15) << 3;
            const uint32_t so = (uint32_t)(vr * FVSTR + vc) * 2;
            CP16(smb + F_V(0) + so,          vH + (size_t)vr * NN + vc);
            CP16(smb + F_V(0) + FVTILE + so, vL + (size_t)vr * NN + vc);
        }
        CP_COMMIT(); CP_WAIT0();
        __syncthreads();

        // ---- Q fragments (cached in regs)
        uint32_t qfh[4][4], qfl[4][4];
#pragma unroll
        for (int kk = 0; kk < 4; ++kk) {
            LDSM4(qfh[kk], smb + F_QHI + aQ + kk * 32);
            LDSM4(qfl[kk], smb + F_QLO + aQ + kk * 32);
        }

        const float mi0 = mask[b * NN + i0 + rw + rloc];
        const float mi1 = mask[b * NN + i0 + rw + rloc + 8];
        const bool rv0 = (mi0 != 0.f);
        const bool rv1 = (mi1 != 0.f);
        float m0 = -1e30f, m1 = -1e30f, l0 = 0.f, l1 = 0.f;
        float oacc[8][4];
#pragma unroll
        for (int i = 0; i < 8; ++i)
#pragma unroll
            for (int j = 0; j < 4; ++j) oacc[i][j] = 0.f;

        for (int kt = 0; kt < 8; ++kt) {
            if (kt + 1 < 8) {
                const int st = (kt + 1) & 1;
                const int j0 = (kt + 1) * 128;
#pragma unroll
                for (int t = 0; t < 4; ++t) {
                    const int idx = tid + t * 256;
                    const int row = idx >> 3;
                    const int col = (idx & 7) << 3;
                    const uint32_t so = (uint32_t)(row * FQSTR + col) * 2;
                    CP16(smb + F_K(st) + so,          kH + (size_t)(j0 + row) * DHH + col);
                    CP16(smb + F_K(st) + FQTILE + so, kL + (size_t)(j0 + row) * DHH + col);
                }
#pragma unroll
                for (int t = 0; t < 4; ++t) {
                    const int idx = tid + t * 256;
                    const int vr = idx >> 4;
                    const int vc = (idx & 15) << 3;
                    const uint32_t so = (uint32_t)(vr * FVSTR + vc) * 2;
                    CP16(smb + F_V(st) + so,          vH + (size_t)vr * NN + j0 + vc);
                    CP16(smb + F_V(st) + FVTILE + so, vL + (size_t)vr * NN + j0 + vc);
                }
                CP_COMMIT();
            }

            const uint32_t kbh = smb + F_K(kt & 1);
            const uint32_t kbl = kbh + FQTILE;
            const uint32_t vbh = smb + F_V(kt & 1);
            const uint32_t vbl = vbh + FVTILE;

            float sacc[16][4];
#pragma unroll
            for (int i = 0; i < 16; ++i)
#pragma unroll
                for (int j = 0; j < 4; ++j) sacc[i][j] = 0.f;
#pragma unroll
            for (int kk = 0; kk < 4; ++kk) {
                const uint32_t kb = kk * 32;
#pragma unroll
                for (int p = 0; p < 8; ++p) {
                    uint32_t tbh[4], tbl[4];
                    LDSM4(tbh, kbh + bkbase + p * 2304 + kb);
                    LDSM4(tbl, kbl + bkbase + p * 2304 + kb);
                    MMA_BF16(sacc[2 * p],     qfh[kk], tbh);
                    MMA_BF16(sacc[2 * p + 1], qfh[kk], tbh + 2);
                    MMA_BF16(sacc[2 * p],     qfh[kk], tbl);
                    MMA_BF16(sacc[2 * p + 1], qfh[kk], tbl + 2);
                    MMA_BF16(sacc[2 * p],     qfl[kk], tbh);
                    MMA_BF16(sacc[2 * p + 1], qfl[kk], tbh + 2);
                }
            }

            const int kt128 = kt * 128;
            float tmax0 = -1e30f, tmax1 = -1e30f;
#pragma unroll
            for (int nt = 0; nt < 16; ++nt) {
                const float2 mv = *(const float2*)(smask + kt128 + nt * 8 + ((lane & 3) << 1));
                const bool g0 = (mv.x != 0.f);
                const bool g1 = (mv.y != 0.f);
                float s0 = (rv0 && g0) ? sacc[nt][0] : -1e30f;
                float s1 = (rv0 && g1) ? sacc[nt][1] : -1e30f;
                float s2 = (rv1 && g0) ? sacc[nt][2] : -1e30f;
                float s3 = (rv1 && g1) ? sacc[nt][3] : -1e30f;
                sacc[nt][0] = s0; sacc[nt][1] = s1; sacc[nt][2] = s2; sacc[nt][3] = s3;
                tmax0 = fmaxf(tmax0, fmaxf(s0, s1));
                tmax1 = fmaxf(tmax1, fmaxf(s2, s3));
            }
            tmax0 = fmaxf(tmax0, __shfl_xor_sync(0xffffffffu, tmax0, 1));
            tmax0 = fmaxf(tmax0, __shfl_xor_sync(0xffffffffu, tmax0, 2));
            tmax1 = fmaxf(tmax1, __shfl_xor_sync(0xffffffffu, tmax1, 1));
            tmax1 = fmaxf(tmax1, __shfl_xor_sync(0xffffffffu, tmax1, 2));
            const float mn0 = fmaxf(m0, tmax0);
            const float mn1 = fmaxf(m1, tmax1);
            const float sc0 = __expf(m0 - mn0);
            const float sc1 = __expf(m1 - mn1);
            m0 = mn0; m1 = mn1;

            float ls0 = 0.f, ls1 = 0.f;
#pragma unroll
            for (int nt = 0; nt < 16; ++nt) {
                float e0 = (sacc[nt][0] > -1e29f) ? __expf(sacc[nt][0] - mn0) : 0.f;
                float e1 = (sacc[nt][1] > -1e29f) ? __expf(sacc[nt][1] - mn0) : 0.f;
                float e2 = (sacc[nt][2] > -1e29f) ? __expf(sacc[nt][2] - mn1) : 0.f;
                float e3 = (sacc[nt][3] > -1e29f) ? __expf(sacc[nt][3] - mn1) : 0.f;
                sacc[nt][0] = e0; sacc[nt][1] = e1; sacc[nt][2] = e2; sacc[nt][3] = e3;
                ls0 += e0 + e1; ls1 += e2 + e3;
            }
            ls0 += __shfl_xor_sync(0xffffffffu, ls0, 1);
            ls0 += __shfl_xor_sync(0xffffffffu, ls0, 2);
            ls1 += __shfl_xor_sync(0xffffffffu, ls1, 1);
            ls1 += __shfl_xor_sync(0xffffffffu, ls1, 2);
            l0 = l0 * sc0 + ls0;
            l1 = l1 * sc1 + ls1;
#pragma unroll
            for (int no = 0; no < 8; ++no) {
                oacc[no][0] *= sc0; oacc[no][1] *= sc0;
                oacc[no][2] *= sc1; oacc[no][3] *= sc1;
            }

#pragma unroll
            for (int kc = 0; kc < 8; ++kc) {
                uint32_t pah[4], pal[4];
                cvt_hilo(sacc[2 * kc][0],     sacc[2 * kc][1],     pah[0], pal[0]);
                cvt_hilo(sacc[2 * kc][2],     sacc[2 * kc][3],     pah[1], pal[1]);
                cvt_hilo(sacc[2 * kc + 1][0], sacc[2 * kc + 1][1], pah[2], pal[2]);
                cvt_hilo(sacc[2 * kc + 1][2], sacc[2 * kc + 1][3], pah[3], pal[3]);
#pragma unroll
                for (int dv = 0; dv < 4; ++dv) {
                    uint32_t vb[4], vl[4];
                    LDSM4(vb, vbh + bvbase + dv * 4352 + kc * 32);
                    LDSM4(vl, vbl + bvbase + dv * 4352 + kc * 32);
                    MMA_BF16(oacc[2 * dv],     pah, vb);
                    MMA_BF16(oacc[2 * dv + 1], pah, vb + 2);
                    MMA_BF16(oacc[2 * dv],     pah, vl);
                    MMA_BF16(oacc[2 * dv + 1], pah, vl + 2);
                    MMA_BF16(oacc[2 * dv],     pal, vb);
                    MMA_BF16(oacc[2 * dv + 1], pal, vb + 2);
                }
            }
            CP_WAIT0();
            __syncthreads();
        }

        const float inv0 = (l0 > 0.f) ? 1.f / l0 : 0.f;
        const float inv1 = (l1 > 0.f) ? 1.f / l1 : 0.f;
        const int r0g = i0 + rw + rloc;
#pragma unroll
        for (int no = 0; no < 8; ++no) {
            const size_t c = (size_t)h * 64 + no * 8 + ((lane & 3) << 1);
            ao[((size_t)b * NN + r0g) * INNERC + c]         = tf32rna(oacc[no][0] * inv0);
            ao[((size_t)b * NN + r0g) * INNERC + c + 1]     = tf32rna(oacc[no][1] * inv0);
            ao[((size_t)b * NN + r0g + 8) * INNERC + c]     = tf32rna(oacc[no][2] * inv1);
            ao[((size_t)b * NN + r0g + 8) * INNERC + c + 1] = tf32rna(oacc[no][3] * inv1);
        }
    }
}

// ---------------------------------------------------------------------------
extern "C" void kernel_launch(void* const* d_in, const int* in_sizes, int n_in,
                              void* d_out, int out_size)
{
    const float* x      = (const float*)d_in[0];
    const float* mask   = (const float*)d_in[1];
    const float* w_qkv  = (const float*)d_in[2];
    const float* w_out  = (const float*)d_in[3];
    const float* b_out  = (const float*)d_in[4];
    float* out = (float*)d_out;

    __nv_bfloat16 *xhi, *xlo, *wqhi, *wqlo;
    __nv_bfloat16 *qhi, *qlo, *khi, *klo, *vThi, *vTlo;
    float *woT, *ao;
    cudaGetSymbolAddress((void**)&xhi, g_xhi);
    cudaGetSymbolAddress((void**)&xlo, g_xlo);
    cudaGetSymbolAddress((void**)&wqhi, g_wqkvThi);
    cudaGetSymbolAddress((void**)&wqlo, g_wqkvTlo);
    cudaGetSymbolAddress((void**)&woT, g_woT);
    cudaGetSymbolAddress((void**)&ao, g_ao);
    cudaGetSymbolAddress((void**)&qhi, g_qhi);
    cudaGetSymbolAddress((void**)&qlo, g_qlo);
    cudaGetSymbolAddress((void**)&khi, g_khi);
    cudaGetSymbolAddress((void**)&klo, g_klo);
    cudaGetSymbolAddress((void**)&vThi, g_vThi);
    cudaGetSymbolAddress((void**)&vTlo, g_vTlo);

    cudaFuncSetAttribute(gemm_qkv, cudaFuncAttributeMaxDynamicSharedMemorySize,
                         QKV_SMEM_BYTES);
    cudaFuncSetAttribute(gemm_out_tf32, cudaFuncAttributeMaxDynamicSharedMemorySize,
                         TF_SMEM_BYTES);
    cudaFuncSetAttribute(flash_tc, cudaFuncAttributeMaxDynamicSharedMemorySize,
                         FLASH_SMEM);

    // 0) prep
    split_kernel<<<(MM * DD / 4 + 255) / 256, 256>>>(x, xhi, xlo, MM * DD / 4);
    splitT_kernel<<<dim3(QKVC / 32, DD / 32), dim3(32, 8)>>>(w_qkv, wqhi, wqlo, DD, QKVC);
    transT_rna<<<dim3(INNERC / 32, INNERC / 32), dim3(32, 8)>>>(w_out, woT,
                                                                INNERC, INNERC);
    // 1) qkv projection (persistent bf16-3, BK=64)
    gemm_qkv<<<NSM, 512, QKV_SMEM_BYTES>>>(
        xhi, xlo, wqhi, wqlo, qhi, qlo, khi, klo, vThi, vTlo);
    // 2) fused masked flash attention (persistent, 256 thr) -> ao fp32(tf32)
    flash_tc<<<NSM, 256, FLASH_SMEM>>>(
        qhi, qlo, khi, klo, vThi, vTlo, mask, ao);
    // 3) out projection (persistent tf32 single-product)
    gemm_out_tf32<<<NSM, 512, TF_SMEM_BYTES>>>(ao, woT, b_out, out);
}

// round 16
// speedup vs baseline: 1.0236x; 1.0236x over previous
#include <cuda_runtime.h>
#include <cuda_bf16.h>
#include <math.h>
#include <cstdint>

// Problem constants
#define BB 4
#define NN 1024
#define DD 1024
#define HH 16
#define DHH 64
#define INNERC 1024          // HH*DHH
#define QKVC 3072            // 3*INNERC
#define MM 4096              // BB*NN
#define BHC 64               // BB*HH
#define NSM 148

// ---------------------------------------------------------------------------
// Scratch (__device__ globals; no allocation allowed)
// ---------------------------------------------------------------------------
__device__ __nv_bfloat16 g_xhi[(size_t)MM * DD];
__device__ __nv_bfloat16 g_xlo[(size_t)MM * DD];
__device__ __nv_bfloat16 g_wqkvThi[(size_t)QKVC * DD];
__device__ __nv_bfloat16 g_wqkvTlo[(size_t)QKVC * DD];
__device__ float g_woT[(size_t)INNERC * INNERC];        // w_out^T, tf32-rounded

// q/k in [B,H,N,DH] bf16 hi/lo (q pre-scaled by 0.125)
__device__ __nv_bfloat16 g_qhi[(size_t)BHC * NN * DHH];
__device__ __nv_bfloat16 g_qlo[(size_t)BHC * NN * DHH];
__device__ __nv_bfloat16 g_khi[(size_t)BHC * NN * DHH];
__device__ __nv_bfloat16 g_klo[(size_t)BHC * NN * DHH];
// v stored directly transposed: [B,H,DH,N]
__device__ __nv_bfloat16 g_vThi[(size_t)BHC * DHH * NN];
__device__ __nv_bfloat16 g_vTlo[(size_t)BHC * DHH * NN];
// attention output fp32 (tf32-rounded), [B*N, INNER]
__device__ float g_ao[(size_t)MM * INNERC];

// ---------------------------------------------------------------------------
// PTX helpers (sm_80-compatible; compile on plain compute_103)
// ---------------------------------------------------------------------------
__device__ __forceinline__ uint32_t smem_u32(const void* p) {
    uint32_t a;
    asm("{ .reg .u64 t; cvta.to.shared.u64 t, %1; cvt.u32.u64 %0, t; }"
        : "=r"(a) : "l"(p));
    return a;
}
#define LDSM4(r, addr) \
    asm volatile("ldmatrix.sync.aligned.m8n8.x4.shared.b16 {%0,%1,%2,%3}, [%4];" \
        : "=r"((r)[0]), "=r"((r)[1]), "=r"((r)[2]), "=r"((r)[3]) : "r"(addr))
#define MMA_BF16(d, a, b) \
    asm volatile("mma.sync.aligned.m16n8k16.row.col.f32.bf16.bf16.f32 " \
        "{%0,%1,%2,%3}, {%4,%5,%6,%7}, {%8,%9}, {%0,%1,%2,%3};" \
        : "+f"((d)[0]), "+f"((d)[1]), "+f"((d)[2]), "+f"((d)[3]) \
        : "r"((a)[0]), "r"((a)[1]), "r"((a)[2]), "r"((a)[3]), \
          "r"((b)[0]), "r"((b)[1]))
#define MMA_TF32(d, a, b) \
    asm volatile("mma.sync.aligned.m16n8k8.row.col.f32.tf32.tf32.f32 " \
        "{%0,%1,%2,%3}, {%4,%5,%6,%7}, {%8,%9}, {%0,%1,%2,%3};" \
        : "+f"((d)[0]), "+f"((d)[1]), "+f"((d)[2]), "+f"((d)[3]) \
        : "r"((a)[0]), "r"((a)[1]), "r"((a)[2]), "r"((a)[3]), \
          "r"((b)[0]), "r"((b)[1]))
#define CP16(saddr, g) \
    asm volatile("cp.async.cg.shared.global [%0], [%1], 16;" :: "r"(saddr), "l"(g))
#define CP_COMMIT() asm volatile("cp.async.commit_group;" ::: "memory")
#define CP_WAIT0()  asm volatile("cp.async.wait_group 0;" ::: "memory")

__device__ __forceinline__ float tf32rna(float x) {
    uint32_t r;
    asm("cvt.rna.tf32.f32 %0, %1;" : "=r"(r) : "f"(x));
    return __uint_as_float(r);
}
__device__ __forceinline__ void store_hilo2(
    __nv_bfloat16* hb, __nv_bfloat16* lb, size_t idx, float a, float b)
{
    __nv_bfloat16 h0 = __float2bfloat16(a);
    __nv_bfloat16 h1 = __float2bfloat16(b);
    *(__nv_bfloat162*)(hb + idx) = __nv_bfloat162(h0, h1);
    *(__nv_bfloat162*)(lb + idx) =
        __nv_bfloat162(__float2bfloat16(a - __bfloat162float(h0)),
                       __float2bfloat16(b - __bfloat162float(h1)));
}
__device__ __forceinline__ void store_hilo1(
    __nv_bfloat16* hb, __nv_bfloat16* lb, size_t idx, float a)
{
    __nv_bfloat16 h0 = __float2bfloat16(a);
    hb[idx] = h0;
    lb[idx] = __float2bfloat16(a - __bfloat162float(h0));
}
__device__ __forceinline__ void cvt_hilo(float a, float b, uint32_t& h, uint32_t& l)
{
    __nv_bfloat16 ha = __float2bfloat16(a);
    __nv_bfloat16 hbb = __float2bfloat16(b);
    __nv_bfloat162 hp(ha, hbb);
    h = *(uint32_t*)&hp;
    __nv_bfloat162 lp(__float2bfloat16(a - __bfloat162float(ha)),
                      __float2bfloat16(b - __bfloat162float(hbb)));
    l = *(uint32_t*)&lp;
}

// ---------------------------------------------------------------------------
// prep kernels
// ---------------------------------------------------------------------------
__global__ void __launch_bounds__(256) split_kernel(
    const float* __restrict__ in, __nv_bfloat16* __restrict__ hi,
    __nv_bfloat16* __restrict__ lo, int n4)
{
    int i = blockIdx.x * 256 + threadIdx.x;
    if (i >= n4) return;
    float4 v = *(const float4*)(in + i * 4);
    store_hilo2(hi, lo, (size_t)i * 4, v.x, v.y);
    store_hilo2(hi, lo, (size_t)i * 4 + 2, v.z, v.w);
}

__global__ void __launch_bounds__(256) splitT_kernel(
    const float* __restrict__ in, __nv_bfloat16* __restrict__ hiT,
    __nv_bfloat16* __restrict__ loT, int R, int C)
{
    __shared__ float t[32][33];
    const int c = blockIdx.x * 32 + threadIdx.x;
#pragma unroll
    for (int j = 0; j < 4; ++j) {
        int r = blockIdx.y * 32 + threadIdx.y + j * 8;
        t[threadIdx.y + j * 8][threadIdx.x] = in[(size_t)r * C + c];
    }
    __syncthreads();
    const int rr = blockIdx.y * 32 + threadIdx.x;
#pragma unroll
    for (int j = 0; j < 4; ++j) {
        int cc = blockIdx.x * 32 + threadIdx.y + j * 8;
        float v = t[threadIdx.x][threadIdx.y + j * 8];
        __nv_bfloat16 h = __float2bfloat16(v);
        hiT[(size_t)cc * R + rr] = h;
        loT[(size_t)cc * R + rr] = __float2bfloat16(v - __bfloat162float(h));
    }
}

// transpose + tf32 RNA rounding (for w_out)
__global__ void __launch_bounds__(256) transT_rna(
    const float* __restrict__ in, float* __restrict__ outT, int R, int C)
{
    __shared__ float t[32][33];
    const int c = blockIdx.x * 32 + threadIdx.x;
#pragma unroll
    for (int j = 0; j < 4; ++j) {
        int r = blockIdx.y * 32 + threadIdx.y + j * 8;
        t[threadIdx.y + j * 8][threadIdx.x] = in[(size_t)r * C + c];
    }
    __syncthreads();
    const int rr = blockIdx.y * 32 + threadIdx.x;
#pragma unroll
    for (int j = 0; j < 4; ++j) {
        int cc = blockIdx.x * 32 + threadIdx.y + j * 8;
        outT[(size_t)cc * R + rr] = tf32rna(t[threadIdx.x][threadIdx.y + j * 8]);
    }
}

// ---------------------------------------------------------------------------
// qkv GEMM: round-13 proven config — BK=32 (stride 40), 16 warps 32x32,
// 2-stage, persistent. Epilogue: q(*0.125)/k hi/lo [B,H,N,DH]; v transposed.
// ---------------------------------------------------------------------------
#define TSTRIDE 40
#define TILEB (128 * TSTRIDE * 2)
#define STAGEB (4 * TILEB)                  // 40960
#define GEMM_SMEM_BYTES (2 * STAGEB)        // 81920

__global__ void __launch_bounds__(512, 1) gemm_qkv(
    const __nv_bfloat16* __restrict__ Ahi, const __nv_bfloat16* __restrict__ Alo,
    const __nv_bfloat16* __restrict__ Bthi, const __nv_bfloat16* __restrict__ Btlo,
    __nv_bfloat16* __restrict__ qhi, __nv_bfloat16* __restrict__ qlo,
    __nv_bfloat16* __restrict__ khi, __nv_bfloat16* __restrict__ klo,
    __nv_bfloat16* __restrict__ vThi, __nv_bfloat16* __restrict__ vTlo)
{
    extern __shared__ char smem[];
    const uint32_t smb = smem_u32(smem);
    const int tid = threadIdx.x;
    const int lane = tid & 31;
    const int wid = tid >> 5;
    const int mw = wid >> 2;
    const int nw = wid & 3;
    const int K = DD;
    const int NT = (QKVC >> 7) * (MM >> 7);   // 768

    const int grow = tid >> 2;
    const int gcol = (tid & 3) << 3;
    const uint32_t stb = (uint32_t)(grow * TSTRIDE + gcol) * 2;

    uint32_t aoff[2];
#pragma unroll
    for (int mt = 0; mt < 2; ++mt)
        aoff[mt] = (uint32_t)((mw * 32 + mt * 16 + (lane & 15)) * TSTRIDE
                              + ((lane >> 4) << 3)) * 2;
    const int brow = nw * 32 + (lane & 7) + ((lane >> 4) << 3);
    const int bcol = ((lane >> 3) & 1) << 3;
    uint32_t boff[2];
    boff[0] = (uint32_t)(brow * TSTRIDE + bcol) * 2;
    boff[1] = (uint32_t)((brow + 16) * TSTRIDE + bcol) * 2;

    const int nst = K >> 5;

    for (int tile = blockIdx.x; tile < NT; tile += NSM) {
        const int m0 = (tile / 24) << 7;
        const int n0 = (tile % 24) << 7;
        const __nv_bfloat16* gAh = Ahi  + (size_t)(m0 + grow) * K + gcol;
        const __nv_bfloat16* gAl = Alo  + (size_t)(m0 + grow) * K + gcol;
        const __nv_bfloat16* gBh = Bthi + (size_t)(n0 + grow) * K + gcol;
        const __nv_bfloat16* gBl = Btlo + (size_t)(n0 + grow) * K + gcol;

        float acc[2][4][4];
#pragma unroll
        for (int i = 0; i < 2; ++i)
#pragma unroll
            for (int j = 0; j < 4; ++j)
#pragma unroll
                for (int k = 0; k < 4; ++k) acc[i][j][k] = 0.f;

        {
            const uint32_t d = smb + stb;
            CP16(d,             gAh);
            CP16(d + TILEB,     gAl);
            CP16(d + 2 * TILEB, gBh);
            CP16(d + 3 * TILEB, gBl);
            CP_COMMIT(); CP_WAIT0();
        }
        __syncthreads();

        for (int s = 0; s < nst; ++s) {
            if (s + 1 < nst) {
                const int k0 = (s + 1) << 5;
                const uint32_t d = smb + ((s + 1) & 1) * STAGEB + stb;
                CP16(d,             gAh + k0);
                CP16(d + TILEB,     gAl + k0);
                CP16(d + 2 * TILEB, gBh + k0);
                CP16(d + 3 * TILEB, gBl + k0);
                CP_COMMIT();
            }
            const uint32_t sb = smb + (s & 1) * STAGEB;
#pragma unroll
            for (int kk = 0; kk < 2; ++kk) {
                const uint32_t kb = kk * 32;
                uint32_t ah[2][4], al[2][4], bh[4][2], bl[4][2];
#pragma unroll
                for (int mt = 0; mt < 2; ++mt) {
                    LDSM4(ah[mt], sb + aoff[mt] + kb);
                    LDSM4(al[mt], sb + TILEB + aoff[mt] + kb);
                }
#pragma unroll
                for (int p = 0; p < 2; ++p) {
                    uint32_t t4[4];
                    LDSM4(t4, sb + 2 * TILEB + boff[p] + kb);
                    bh[2 * p][0] = t4[0]; bh[2 * p][1] = t4[1];
                    bh[2 * p + 1][0] = t4[2]; bh[2 * p + 1][1] = t4[3];
                    LDSM4(t4, sb + 3 * TILEB + boff[p] + kb);
                    bl[2 * p][0] = t4[0]; bl[2 * p][1] = t4[1];
                    bl[2 * p + 1][0] = t4[2]; bl[2 * p + 1][1] = t4[3];
                }
#pragma unroll
                for (int mt = 0; mt < 2; ++mt)
#pragma unroll
                    for (int nt = 0; nt < 4; ++nt)
                        MMA_BF16(acc[mt][nt], ah[mt], bh[nt]);
#pragma unroll
                for (int mt = 0; mt < 2; ++mt)
#pragma unroll
                    for (int nt = 0; nt < 4; ++nt)
                        MMA_BF16(acc[mt][nt], ah[mt], bl[nt]);
#pragma unroll
                for (int mt = 0; mt < 2; ++mt)
#pragma unroll
                    for (int nt = 0; nt < 4; ++nt)
                        MMA_BF16(acc[mt][nt], al[mt], bh[nt]);
            }
            CP_WAIT0();
            __syncthreads();
        }

        // epilogue: q (*0.125) / k in [B,H,N,DH]; v transposed into [B,H,DH,N]
#pragma unroll
        for (int nt = 0; nt < 4; ++nt) {
            const int cc = n0 + nw * 32 + nt * 8 + ((lane & 3) << 1);
            const int sec = cc >> 10;
            const int h = (cc & 1023) >> 6;
            const int d = cc & 63;
#pragma unroll
            for (int mt = 0; mt < 2; ++mt) {
                const int r0 = m0 + mw * 32 + mt * 16 + (lane >> 2);
                const int b = r0 >> 10;
                const int n = r0 & 1023;
                const size_t bhbase = ((size_t)b * HH + h);
                if (sec == 0) {
                    store_hilo2(qhi, qlo, (bhbase * NN + n) * DHH + d,
                                acc[mt][nt][0] * 0.125f, acc[mt][nt][1] * 0.125f);
                    store_hilo2(qhi, qlo, (bhbase * NN + n + 8) * DHH + d,
                                acc[mt][nt][2] * 0.125f, acc[mt][nt][3] * 0.125f);
                } else if (sec == 1) {
                    store_hilo2(khi, klo, (bhbase * NN + n) * DHH + d,
                                acc[mt][nt][0], acc[mt][nt][1]);
                    store_hilo2(khi, klo, (bhbase * NN + n + 8) * DHH + d,
                                acc[mt][nt][2], acc[mt][nt][3]);
                } else {
                    const size_t vb = bhbase * DHH;
                    store_hilo1(vThi, vTlo, (vb + d) * NN + n,         acc[mt][nt][0]);
                    store_hilo1(vThi, vTlo, (vb + d + 1) * NN + n,     acc[mt][nt][1]);
                    store_hilo1(vThi, vTlo, (vb + d) * NN + n + 8,     acc[mt][nt][2]);
                    store_hilo1(vThi, vTlo, (vb + d + 1) * NN + n + 8, acc[mt][nt][3]);
                }
            }
        }
    }
}

// ---------------------------------------------------------------------------
// tf32 out-projection GEMM: out = ao @ woT^T + bias (round-14 proven)
// ---------------------------------------------------------------------------
#define TFSTR 36
#define TFTILEB (128 * TFSTR * 4)           // 18432
#define TFSTAGEB (2 * TFTILEB)              // 36864
#define TF_SMEM_BYTES (2 * TFSTAGEB)        // 73728

__global__ void __launch_bounds__(512, 1) gemm_out_tf32(
    const float* __restrict__ A, const float* __restrict__ Bt,
    const float* __restrict__ bias, float* __restrict__ C)
{
    extern __shared__ char smem[];
    const uint32_t smb = smem_u32(smem);
    const int tid = threadIdx.x;
    const int lane = tid & 31;
    const int wid = tid >> 5;
    const int mw = wid >> 2;
    const int nw = wid & 3;
    const int NT = (MM >> 7) * (INNERC >> 7);   // 256

    const int grow = tid >> 2;
    const int gcolf = (tid & 3) << 3;
    const uint32_t stb = (uint32_t)(grow * TFSTR + gcolf) * 4;

    const int mat = lane >> 3;
    const int rr = lane & 7;
    uint32_t aoff[2];
#pragma unroll
    for (int mt = 0; mt < 2; ++mt)
        aoff[mt] = (uint32_t)((mw * 32 + mt * 16 + ((mat & 1) << 3) + rr) * TFSTR
                              + ((mat >> 1) << 2)) * 4;
    uint32_t boff[2];
#pragma unroll
    for (int p = 0; p < 2; ++p)
        boff[p] = (uint32_t)((nw * 32 + p * 16 + ((mat >> 1) << 3) + rr) * TFSTR
                             + ((mat & 1) << 2)) * 4;

    const int nst = INNERC >> 5;   // 32

    for (int tile = blockIdx.x; tile < NT; tile += NSM) {
        const int m0 = (tile >> 3) << 7;
        const int n0 = (tile & 7) << 7;
        const float* gA = A  + (size_t)(m0 + grow) * INNERC + gcolf;
        const float* gB = Bt + (size_t)(n0 + grow) * INNERC + gcolf;

        float acc[2][4][4];
#pragma unroll
        for (int i = 0; i < 2; ++i)
#pragma unroll
            for (int j = 0; j < 4; ++j)
#pragma unroll
                for (int k = 0; k < 4; ++k) acc[i][j][k] = 0.f;

        {
            const uint32_t d = smb + stb;
            CP16(d,      gA); CP16(d + 16,      gA + 4);
            CP16(d + TFTILEB, gB); CP16(d + TFTILEB + 16, gB + 4);
            CP_COMMIT(); CP_WAIT0();
        }
        __syncthreads();

        for (int s = 0; s < nst; ++s) {
            if (s + 1 < nst) {
                const int k0 = (s + 1) << 5;
                const uint32_t d = smb + ((s + 1) & 1) * TFSTAGEB + stb;
                CP16(d,      gA + k0); CP16(d + 16,      gA + k0 + 4);
                CP16(d + TFTILEB, gB + k0); CP16(d + TFTILEB + 16, gB + k0 + 4);
                CP_COMMIT();
            }
            const uint32_t sb = smb + (s & 1) * TFSTAGEB;
#pragma unroll
            for (int kc = 0; kc < 4; ++kc) {
                const uint32_t kb = kc * 32;
                uint32_t af[2][4], bf[4][2];
#pragma unroll
                for (int mt = 0; mt < 2; ++mt)
                    LDSM4(af[mt], sb + aoff[mt] + kb);
#pragma unroll
                for (int p = 0; p < 2; ++p) {
                    uint32_t t4[4];
                    LDSM4(t4, sb + TFTILEB + boff[p] + kb);
                    bf[2 * p][0] = t4[0]; bf[2 * p][1] = t4[1];
                    bf[2 * p + 1][0] = t4[2]; bf[2 * p + 1][1] = t4[3];
                }
#pragma unroll
                for (int mt = 0; mt < 2; ++mt)
#pragma unroll
                    for (int nt = 0; nt < 4; ++nt)
                        MMA_TF32(acc[mt][nt], af[mt], bf[nt]);
            }
            CP_WAIT0();
            __syncthreads();
        }

#pragma unroll
        for (int mt = 0; mt < 2; ++mt) {
            const int r0 = m0 + mw * 32 + mt * 16 + (lane >> 2);
#pragma unroll
            for (int nt = 0; nt < 4; ++nt) {
                const int cc = n0 + nw * 32 + nt * 8 + ((lane & 3) << 1);
                float2 bv = *(const float2*)(bias + cc);
                float2 v0 = make_float2(acc[mt][nt][0] + bv.x, acc[mt][nt][1] + bv.y);
                float2 v1 = make_float2(acc[mt][nt][2] + bv.x, acc[mt][nt][3] + bv.y);
                *(float2*)(C + (size_t)r0 * INNERC + cc) = v0;
                *(float2*)(C + (size_t)(r0 + 8) * INNERC + cc) = v1;
            }
        }
    }
}

// ---------------------------------------------------------------------------
// flash_tc: fused masked attention, 256 threads (round-13 proven structure),
// persistent; epilogue writes fp32 (tf32-rounded) ao.
// ---------------------------------------------------------------------------
#define FQSTR 72
#define FQTILE 18432                      // 128*72*2
#define FVSTR 136
#define FVTILE 17408                      // 64*136*2
#define F_MASK 0
#define F_QHI 4096
#define F_QLO (F_QHI + FQTILE)
#define F_K(st) (40960 + (st) * 2 * FQTILE)
#define F_V(st) (114688 + (st) * 2 * FVTILE)
#define FLASH_SMEM 184320

__global__ void __launch_bounds__(256, 1) flash_tc(
    const __nv_bfloat16* __restrict__ qhi, const __nv_bfloat16* __restrict__ qlo,
    const __nv_bfloat16* __restrict__ khi, const __nv_bfloat16* __restrict__ klo,
    const __nv_bfloat16* __restrict__ vThi, const __nv_bfloat16* __restrict__ vTlo,
    const float* __restrict__ mask, float* __restrict__ ao)
{
    extern __shared__ char smem[];
    const uint32_t smb = smem_u32(smem);
    const int tid = threadIdx.x;
    const int lane = tid & 31;
    const int wid = tid >> 5;
    const int rw = wid * 16;
    const int rloc = lane >> 2;

    const uint32_t bkbase = (uint32_t)(((lane & 7) + ((lane >> 4) << 3)) * FQSTR
                                       + (((lane >> 3) & 1) << 3)) * 2;
    const uint32_t bvbase = (uint32_t)(((lane & 7) + ((lane >> 4) << 3)) * FVSTR
                                       + (((lane >> 3) & 1) << 3)) * 2;
    const uint32_t aQ = (uint32_t)((rw + (lane & 15)) * FQSTR + ((lane >> 4) << 3)) * 2;
    const float* smask = (const float*)smem;

    for (int tile = blockIdx.x; tile < 512; tile += NSM) {
        const int bh = tile >> 3;
        const int i0 = (tile & 7) << 7;
        const int b = bh >> 4;
        const int h = bh & 15;
        const size_t hb = (size_t)bh * NN * DHH;
        const __nv_bfloat16* kH = khi + hb;
        const __nv_bfloat16* kL = klo + hb;
        const __nv_bfloat16* vH = vThi + (size_t)bh * DHH * NN;
        const __nv_bfloat16* vL = vTlo + (size_t)bh * DHH * NN;

        // ---- prologue: mask + Q + K0 + V0 via cp.async
        CP16(smb + F_MASK + tid * 16, mask + b * NN + tid * 4);
#pragma unroll
        for (int t = 0; t < 4; ++t) {
            const int idx = tid + t * 256;
            const int row = idx >> 3;
            const int col = (idx & 7) << 3;
            const uint32_t so = (uint32_t)(row * FQSTR + col) * 2;
            CP16(smb + F_QHI + so, qhi + hb + (size_t)(i0 + row) * DHH + col);
            CP16(smb + F_QLO + so, qlo + hb + (size_t)(i0 + row) * DHH + col);
            CP16(smb + F_K(0) + so,          kH + (size_t)row * DHH + col);
            CP16(smb + F_K(0) + FQTILE + so, kL + (size_t)row * DHH + col);
        }
#pragma unroll
        for (int t = 0; t < 4; ++t) {
            const int idx = tid + t * 256;
            const int vr = idx >> 4;
            const int vc = (idx & 15) << 3;
            const uint32_t so = (uint32_t)(vr * FVSTR + vc) * 2;
            CP16(smb + F_V(0) + so,          vH + (size_t)vr * NN + vc);
            CP16(smb + F_V(0) + FVTILE + so, vL + (size_t)vr * NN + vc);
        }
        CP_COMMIT(); CP_WAIT0();
        __syncthreads();

        // ---- Q fragments (cached in regs)
        uint32_t qfh[4][4], qfl[4][4];
#pragma unroll
        for (int kk = 0; kk < 4; ++kk) {
            LDSM4(qfh[kk], smb + F_QHI + aQ + kk * 32);
            LDSM4(qfl[kk], smb + F_QLO + aQ + kk * 32);
        }

        const float mi0 = mask[b * NN + i0 + rw + rloc];
        const float mi1 = mask[b * NN + i0 + rw + rloc + 8];
        const bool rv0 = (mi0 != 0.f);
        const bool rv1 = (mi1 != 0.f);
        float m0 = -1e30f, m1 = -1e30f, l0 = 0.f, l1 = 0.f;
        float oacc[8][4];
#pragma unroll
        for (int i = 0; i < 8; ++i)
#pragma unroll
            for (int j = 0; j < 4; ++j) oacc[i][j] = 0.f;

        for (int kt = 0; kt < 8; ++kt) {
            if (kt + 1 < 8) {
                const int st = (kt + 1) & 1;
                const int j0 = (kt + 1) * 128;
#pragma unroll
                for (int t = 0; t < 4; ++t) {
                    const int idx = tid + t * 256;
                    const int row = idx >> 3;
                    const int col = (idx & 7) << 3;
                    const uint32_t so = (uint32_t)(row * FQSTR + col) * 2;
                    CP16(smb + F_K(st) + so,          kH + (size_t)(j0 + row) * DHH + col);
                    CP16(smb + F_K(st) + FQTILE + so, kL + (size_t)(j0 + row) * DHH + col);
                }
#pragma unroll
                for (int t = 0; t < 4; ++t) {
                    const int idx = tid + t * 256;
                    const int vr = idx >> 4;
                    const int vc = (idx & 15) << 3;
                    const uint32_t so = (uint32_t)(vr * FVSTR + vc) * 2;
                    CP16(smb + F_V(st) + so,          vH + (size_t)vr * NN + j0 + vc);
                    CP16(smb + F_V(st) + FVTILE + so, vL + (size_t)vr * NN + j0 + vc);
                }
                CP_COMMIT();
            }

            const uint32_t kbh = smb + F_K(kt & 1);
            const uint32_t kbl = kbh + FQTILE;
            const uint32_t vbh = smb + F_V(kt & 1);
            const uint32_t vbl = vbh + FVTILE;

            float sacc[16][4];
#pragma unroll
            for (int i = 0; i < 16; ++i)
#pragma unroll
                for (int j = 0; j < 4; ++j) sacc[i][j] = 0.f;
#pragma unroll
            for (int kk = 0; kk < 4; ++kk) {
                const uint32_t kb = kk * 32;
#pragma unroll
                for (int p = 0; p < 8; ++p) {
                    uint32_t tbh[4], tbl[4];
                    LDSM4(tbh, kbh + bkbase + p * 2304 + kb);
                    LDSM4(tbl, kbl + bkbase + p * 2304 + kb);
                    MMA_BF16(sacc[2 * p],     qfh[kk], tbh);
                    MMA_BF16(sacc[2 * p + 1], qfh[kk], tbh + 2);
                    MMA_BF16(sacc[2 * p],     qfh[kk], tbl);
                    MMA_BF16(sacc[2 * p + 1], qfh[kk], tbl + 2);
                    MMA_BF16(sacc[2 * p],     qfl[kk], tbh);
                    MMA_BF16(sacc[2 * p + 1], qfl[kk], tbh + 2);
                }
            }

            const int kt128 = kt * 128;
            float tmax0 = -1e30f, tmax1 = -1e30f;
#pragma unroll
            for (int nt = 0; nt < 16; ++nt) {
                const float2 mv = *(const float2*)(smask + kt128 + nt * 8 + ((lane & 3) << 1));
                const bool g0 = (mv.x != 0.f);
                const bool g1 = (mv.y != 0.f);
                float s0 = (rv0 && g0) ? sacc[nt][0] : -1e30f;
                float s1 = (rv0 && g1) ? sacc[nt][1] : -1e30f;
                float s2 = (rv1 && g0) ? sacc[nt][2] : -1e30f;
                float s3 = (rv1 && g1) ? sacc[nt][3] : -1e30f;
                sacc[nt][0] = s0; sacc[nt][1] = s1; sacc[nt][2] = s2; sacc[nt][3] = s3;
                tmax0 = fmaxf(tmax0, fmaxf(s0, s1));
                tmax1 = fmaxf(tmax1, fmaxf(s2, s3));
            }
            tmax0 = fmaxf(tmax0, __shfl_xor_sync(0xffffffffu, tmax0, 1));
            tmax0 = fmaxf(tmax0, __shfl_xor_sync(0xffffffffu, tmax0, 2));
            tmax1 = fmaxf(tmax1, __shfl_xor_sync(0xffffffffu, tmax1, 1));
            tmax1 = fmaxf(tmax1, __shfl_xor_sync(0xffffffffu, tmax1, 2));
            const float mn0 = fmaxf(m0, tmax0);
            const float mn1 = fmaxf(m1, tmax1);
            const float sc0 = __expf(m0 - mn0);
            const float sc1 = __expf(m1 - mn1);
            m0 = mn0; m1 = mn1;

            float ls0 = 0.f, ls1 = 0.f;
#pragma unroll
            for (int nt = 0; nt < 16; ++nt) {
                float e0 = (sacc[nt][0] > -1e29f) ? __expf(sacc[nt][0] - mn0) : 0.f;
                float e1 = (sacc[nt][1] > -1e29f) ? __expf(sacc[nt][1] - mn0) : 0.f;
                float e2 = (sacc[nt][2] > -1e29f) ? __expf(sacc[nt][2] - mn1) : 0.f;
                float e3 = (sacc[nt][3] > -1e29f) ? __expf(sacc[nt][3] - mn1) : 0.f;
                sacc[nt][0] = e0; sacc[nt][1] = e1; sacc[nt][2] = e2; sacc[nt][3] = e3;
                ls0 += e0 + e1; ls1 += e2 + e3;
            }
            ls0 += __shfl_xor_sync(0xffffffffu, ls0, 1);
            ls0 += __shfl_xor_sync(0xffffffffu, ls0, 2);
            ls1 += __shfl_xor_sync(0xffffffffu, ls1, 1);
            ls1 += __shfl_xor_sync(0xffffffffu, ls1, 2);
            l0 = l0 * sc0 + ls0;
            l1 = l1 * sc1 + ls1;
#pragma unroll
            for (int no = 0; no < 8; ++no) {
                oacc[no][0] *= sc0; oacc[no][1] *= sc0;
                oacc[no][2] *= sc1; oacc[no][3] *= sc1;
            }

#pragma unroll
            for (int kc = 0; kc < 8; ++kc) {
                uint32_t pah[4], pal[4];
                cvt_hilo(sacc[2 * kc][0],     sacc[2 * kc][1],     pah[0], pal[0]);
                cvt_hilo(sacc[2 * kc][2],     sacc[2 * kc][3],     pah[1], pal[1]);
                cvt_hilo(sacc[2 * kc + 1][0], sacc[2 * kc + 1][1], pah[2], pal[2]);
                cvt_hilo(sacc[2 * kc + 1][2], sacc[2 * kc + 1][3], pah[3], pal[3]);
#pragma unroll
                for (int dv = 0; dv < 4; ++dv) {
                    uint32_t vb[4], vl[4];
                    LDSM4(vb, vbh + bvbase + dv * 4352 + kc * 32);
                    LDSM4(vl, vbl + bvbase + dv * 4352 + kc * 32);
                    MMA_BF16(oacc[2 * dv],     pah, vb);
                    MMA_BF16(oacc[2 * dv + 1], pah, vb + 2);
                    MMA_BF16(oacc[2 * dv],     pah, vl);
                    MMA_BF16(oacc[2 * dv + 1], pah, vl + 2);
                    MMA_BF16(oacc[2 * dv],     pal, vb);
                    MMA_BF16(oacc[2 * dv + 1], pal, vb + 2);
                }
            }
            CP_WAIT0();
            __syncthreads();
        }

        const float inv0 = (l0 > 0.f) ? 1.f / l0 : 0.f;
        const float inv1 = (l1 > 0.f) ? 1.f / l1 : 0.f;
        const int r0g = i0 + rw + rloc;
#pragma unroll
        for (int no = 0; no < 8; ++no) {
            const size_t c = (size_t)h * 64 + no * 8 + ((lane & 3) << 1);
            ao[((size_t)b * NN + r0g) * INNERC + c]         = tf32rna(oacc[no][0] * inv0);
            ao[((size_t)b * NN + r0g) * INNERC + c + 1]     = tf32rna(oacc[no][1] * inv0);
            ao[((size_t)b * NN + r0g + 8) * INNERC + c]     = tf32rna(oacc[no][2] * inv1);
            ao[((size_t)b * NN + r0g + 8) * INNERC + c + 1] = tf32rna(oacc[no][3] * inv1);
        }
    }
}

// ---------------------------------------------------------------------------
extern "C" void kernel_launch(void* const* d_in, const int* in_sizes, int n_in,
                              void* d_out, int out_size)
{
    const float* x      = (const float*)d_in[0];
    const float* mask   = (const float*)d_in[1];
    const float* w_qkv  = (const float*)d_in[2];
    const float* w_out  = (const float*)d_in[3];
    const float* b_out  = (const float*)d_in[4];
    float* out = (float*)d_out;

    __nv_bfloat16 *xhi, *xlo, *wqhi, *wqlo;
    __nv_bfloat16 *qhi, *qlo, *khi, *klo, *vThi, *vTlo;
    float *woT, *ao;
    cudaGetSymbolAddress((void**)&xhi, g_xhi);
    cudaGetSymbolAddress((void**)&xlo, g_xlo);
    cudaGetSymbolAddress((void**)&wqhi, g_wqkvThi);
    cudaGetSymbolAddress((void**)&wqlo, g_wqkvTlo);
    cudaGetSymbolAddress((void**)&woT, g_woT);
    cudaGetSymbolAddress((void**)&ao, g_ao);
    cudaGetSymbolAddress((void**)&qhi, g_qhi);
    cudaGetSymbolAddress((void**)&qlo, g_qlo);
    cudaGetSymbolAddress((void**)&khi, g_khi);
    cudaGetSymbolAddress((void**)&klo, g_klo);
    cudaGetSymbolAddress((void**)&vThi, g_vThi);
    cudaGetSymbolAddress((void**)&vTlo, g_vTlo);

    cudaFuncSetAttribute(gemm_qkv, cudaFuncAttributeMaxDynamicSharedMemorySize,
                         GEMM_SMEM_BYTES);
    cudaFuncSetAttribute(gemm_out_tf32, cudaFuncAttributeMaxDynamicSharedMemorySize,
                         TF_SMEM_BYTES);
    cudaFuncSetAttribute(flash_tc, cudaFuncAttributeMaxDynamicSharedMemorySize,
                         FLASH_SMEM);

    // 0) prep
    split_kernel<<<(MM * DD / 4 + 255) / 256, 256>>>(x, xhi, xlo, MM * DD / 4);
    splitT_kernel<<<dim3(QKVC / 32, DD / 32), dim3(32, 8)>>>(w_qkv, wqhi, wqlo, DD, QKVC);
    transT_rna<<<dim3(INNERC / 32, INNERC / 32), dim3(32, 8)>>>(w_out, woT,
                                                                INNERC, INNERC);
    // 1) qkv projection (persistent bf16-3, BK=32 proven config)
    gemm_qkv<<<NSM, 512, GEMM_SMEM_BYTES>>>(
        xhi, xlo, wqhi, wqlo, qhi, qlo, khi, klo, vThi, vTlo);
    // 2) fused masked flash attention (persistent, 256 thr) -> ao fp32(tf32)
    flash_tc<<<NSM, 256, FLASH_SMEM>>>(
        qhi, qlo, khi, klo, vThi, vTlo, mask, ao);
    // 3) out projection (persistent tf32 single-product)
    gemm_out_tf32<<<NSM, 512, TF_SMEM_BYTES>>>(ao, woT, b_out, out);
}

// round 17
// speedup vs baseline: 1.0315x; 1.0077x over previous
#include <cuda_runtime.h>
#include <cuda_bf16.h>
#include <math.h>
#include <cstdint>

// Problem constants
#define BB 4
#define NN 1024
#define DD 1024
#define HH 16
#define DHH 64
#define INNERC 1024          // HH*DHH
#define QKVC 3072            // 3*INNERC
#define MM 4096              // BB*NN
#define BHC 64               // BB*HH
#define NSM 148

// ---------------------------------------------------------------------------
// Scratch (__device__ globals; no allocation allowed)
// ---------------------------------------------------------------------------
__device__ __nv_bfloat16 g_xhi[(size_t)MM * DD];
__device__ __nv_bfloat16 g_xlo[(size_t)MM * DD];
__device__ float g_xtf[(size_t)MM * DD];                // x, tf32-rounded
__device__ __nv_bfloat16 g_wqkvThi[(size_t)(2 * INNERC) * DD];  // q,k cols only
__device__ __nv_bfloat16 g_wqkvTlo[(size_t)(2 * INNERC) * DD];
__device__ float g_wvT[(size_t)INNERC * DD];            // v weight slab^T, rna
__device__ float g_woT[(size_t)INNERC * INNERC];        // w_out^T, tf32-rounded

// q/k in [B,H,N,DH] bf16 hi/lo (q pre-scaled by 0.125)
__device__ __nv_bfloat16 g_qhi[(size_t)BHC * NN * DHH];
__device__ __nv_bfloat16 g_qlo[(size_t)BHC * NN * DHH];
__device__ __nv_bfloat16 g_khi[(size_t)BHC * NN * DHH];
__device__ __nv_bfloat16 g_klo[(size_t)BHC * NN * DHH];
// v stored directly transposed: [B,H,DH,N]
__device__ __nv_bfloat16 g_vThi[(size_t)BHC * DHH * NN];
__device__ __nv_bfloat16 g_vTlo[(size_t)BHC * DHH * NN];
// attention output fp32 (tf32-rounded), [B*N, INNER]
__device__ float g_ao[(size_t)MM * INNERC];

// ---------------------------------------------------------------------------
// PTX helpers
// ---------------------------------------------------------------------------
__device__ __forceinline__ uint32_t smem_u32(const void* p) {
    uint32_t a;
    asm("{ .reg .u64 t; cvta.to.shared.u64 t, %1; cvt.u32.u64 %0, t; }"
        : "=r"(a) : "l"(p));
    return a;
}
#define LDSM4(r, addr) \
    asm volatile("ldmatrix.sync.aligned.m8n8.x4.shared.b16 {%0,%1,%2,%3}, [%4];" \
        : "=r"((r)[0]), "=r"((r)[1]), "=r"((r)[2]), "=r"((r)[3]) : "r"(addr))
#define MMA_BF16(d, a, b) \
    asm volatile("mma.sync.aligned.m16n8k16.row.col.f32.bf16.bf16.f32 " \
        "{%0,%1,%2,%3}, {%4,%5,%6,%7}, {%8,%9}, {%0,%1,%2,%3};" \
        : "+f"((d)[0]), "+f"((d)[1]), "+f"((d)[2]), "+f"((d)[3]) \
        : "r"((a)[0]), "r"((a)[1]), "r"((a)[2]), "r"((a)[3]), \
          "r"((b)[0]), "r"((b)[1]))
#define MMA_TF32(d, a, b) \
    asm volatile("mma.sync.aligned.m16n8k8.row.col.f32.tf32.tf32.f32 " \
        "{%0,%1,%2,%3}, {%4,%5,%6,%7}, {%8,%9}, {%0,%1,%2,%3};" \
        : "+f"((d)[0]), "+f"((d)[1]), "+f"((d)[2]), "+f"((d)[3]) \
        : "r"((a)[0]), "r"((a)[1]), "r"((a)[2]), "r"((a)[3]), \
          "r"((b)[0]), "r"((b)[1]))
#define CP16(saddr, g) \
    asm volatile("cp.async.cg.shared.global [%0], [%1], 16;" :: "r"(saddr), "l"(g))
#define CP_COMMIT() asm volatile("cp.async.commit_group;" ::: "memory")
#define CP_WAIT0()  asm volatile("cp.async.wait_group 0;" ::: "memory")

__device__ __forceinline__ float tf32rna(float x) {
    uint32_t r;
    asm("cvt.rna.tf32.f32 %0, %1;" : "=r"(r) : "f"(x));
    return __uint_as_float(r);
}
__device__ __forceinline__ void store_hilo2(
    __nv_bfloat16* hb, __nv_bfloat16* lb, size_t idx, float a, float b)
{
    __nv_bfloat16 h0 = __float2bfloat16(a);
    __nv_bfloat16 h1 = __float2bfloat16(b);
    *(__nv_bfloat162*)(hb + idx) = __nv_bfloat162(h0, h1);
    *(__nv_bfloat162*)(lb + idx) =
        __nv_bfloat162(__float2bfloat16(a - __bfloat162float(h0)),
                       __float2bfloat16(b - __bfloat162float(h1)));
}
__device__ __forceinline__ void store_hilo1(
    __nv_bfloat16* hb, __nv_bfloat16* lb, size_t idx, float a)
{
    __nv_bfloat16 h0 = __float2bfloat16(a);
    hb[idx] = h0;
    lb[idx] = __float2bfloat16(a - __bfloat162float(h0));
}
__device__ __forceinline__ void cvt_hilo(float a, float b, uint32_t& h, uint32_t& l)
{
    __nv_bfloat16 ha = __float2bfloat16(a);
    __nv_bfloat16 hbb = __float2bfloat16(b);
    __nv_bfloat162 hp(ha, hbb);
    h = *(uint32_t*)&hp;
    __nv_bfloat162 lp(__float2bfloat16(a - __bfloat162float(ha)),
                      __float2bfloat16(b - __bfloat162float(hbb)));
    l = *(uint32_t*)&lp;
}

// ---------------------------------------------------------------------------
// prep kernels
// ---------------------------------------------------------------------------
// x -> bf16 hi/lo AND tf32-rounded fp32
__global__ void __launch_bounds__(256) split_kernel(
    const float* __restrict__ in, __nv_bfloat16* __restrict__ hi,
    __nv_bfloat16* __restrict__ lo, float* __restrict__ tf, int n4)
{
    int i = blockIdx.x * 256 + threadIdx.x;
    if (i >= n4) return;
    float4 v = *(const float4*)(in + i * 4);
    store_hilo2(hi, lo, (size_t)i * 4, v.x, v.y);
    store_hilo2(hi, lo, (size_t)i * 4 + 2, v.z, v.w);
    float4 t = make_float4(tf32rna(v.x), tf32rna(v.y), tf32rna(v.z), tf32rna(v.w));
    *(float4*)(tf + (size_t)i * 4) = t;
}

__global__ void __launch_bounds__(256) splitT_kernel(
    const float* __restrict__ in, __nv_bfloat16* __restrict__ hiT,
    __nv_bfloat16* __restrict__ loT, int R, int C)
{
    __shared__ float t[32][33];
    const int c = blockIdx.x * 32 + threadIdx.x;
#pragma unroll
    for (int j = 0; j < 4; ++j) {
        int r = blockIdx.y * 32 + threadIdx.y + j * 8;
        t[threadIdx.y + j * 8][threadIdx.x] = in[(size_t)r * C + c];
    }
    __syncthreads();
    const int rr = blockIdx.y * 32 + threadIdx.x;
#pragma unroll
    for (int j = 0; j < 4; ++j) {
        int cc = blockIdx.x * 32 + threadIdx.y + j * 8;
        float v = t[threadIdx.x][threadIdx.y + j * 8];
        __nv_bfloat16 h = __float2bfloat16(v);
        hiT[(size_t)cc * R + rr] = h;
        loT[(size_t)cc * R + rr] = __float2bfloat16(v - __bfloat162float(h));
    }
}

// transpose + tf32 RNA rounding
__global__ void __launch_bounds__(256) transT_rna(
    const float* __restrict__ in, float* __restrict__ outT, int R, int C)
{
    __shared__ float t[32][33];
    const int c = blockIdx.x * 32 + threadIdx.x;
#pragma unroll
    for (int j = 0; j < 4; ++j) {
        int r = blockIdx.y * 32 + threadIdx.y + j * 8;
        t[threadIdx.y + j * 8][threadIdx.x] = in[(size_t)r * C + c];
    }
    __syncthreads();
    const int rr = blockIdx.y * 32 + threadIdx.x;
#pragma unroll
    for (int j = 0; j < 4; ++j) {
        int cc = blockIdx.x * 32 + threadIdx.y + j * 8;
        outT[(size_t)cc * R + rr] = tf32rna(t[threadIdx.x][threadIdx.y + j * 8]);
    }
}

// ---------------------------------------------------------------------------
// q/k GEMM: proven BK=32 bf16-3 config, persistent; 512 tiles (q,k cols only).
// ---------------------------------------------------------------------------
#define TSTRIDE 40
#define TILEB (128 * TSTRIDE * 2)
#define STAGEB (4 * TILEB)                  // 40960
#define GEMM_SMEM_BYTES (2 * STAGEB)        // 81920

__global__ void __launch_bounds__(512, 1) gemm_qk(
    const __nv_bfloat16* __restrict__ Ahi, const __nv_bfloat16* __restrict__ Alo,
    const __nv_bfloat16* __restrict__ Bthi, const __nv_bfloat16* __restrict__ Btlo,
    __nv_bfloat16* __restrict__ qhi, __nv_bfloat16* __restrict__ qlo,
    __nv_bfloat16* __restrict__ khi, __nv_bfloat16* __restrict__ klo)
{
    extern __shared__ char smem[];
    const uint32_t smb = smem_u32(smem);
    const int tid = threadIdx.x;
    const int lane = tid & 31;
    const int wid = tid >> 5;
    const int mw = wid >> 2;
    const int nw = wid & 3;
    const int K = DD;
    const int NT = 16 * (MM >> 7);   // 16 n-tiles (2048 cols) * 32 m-tiles = 512

    const int grow = tid >> 2;
    const int gcol = (tid & 3) << 3;
    const uint32_t stb = (uint32_t)(grow * TSTRIDE + gcol) * 2;

    uint32_t aoff[2];
#pragma unroll
    for (int mt = 0; mt < 2; ++mt)
        aoff[mt] = (uint32_t)((mw * 32 + mt * 16 + (lane & 15)) * TSTRIDE
                              + ((lane >> 4) << 3)) * 2;
    const int brow = nw * 32 + (lane & 7) + ((lane >> 4) << 3);
    const int bcol = ((lane >> 3) & 1) << 3;
    uint32_t boff[2];
    boff[0] = (uint32_t)(brow * TSTRIDE + bcol) * 2;
    boff[1] = (uint32_t)((brow + 16) * TSTRIDE + bcol) * 2;

    const int nst = K >> 5;

    for (int tile = blockIdx.x; tile < NT; tile += NSM) {
        const int m0 = (tile >> 4) << 7;
        const int n0 = (tile & 15) << 7;
        const __nv_bfloat16* gAh = Ahi  + (size_t)(m0 + grow) * K + gcol;
        const __nv_bfloat16* gAl = Alo  + (size_t)(m0 + grow) * K + gcol;
        const __nv_bfloat16* gBh = Bthi + (size_t)(n0 + grow) * K + gcol;
        const __nv_bfloat16* gBl = Btlo + (size_t)(n0 + grow) * K + gcol;

        float acc[2][4][4];
#pragma unroll
        for (int i = 0; i < 2; ++i)
#pragma unroll
            for (int j = 0; j < 4; ++j)
#pragma unroll
                for (int k = 0; k < 4; ++k) acc[i][j][k] = 0.f;

        {
            const uint32_t d = smb + stb;
            CP16(d,             gAh);
            CP16(d + TILEB,     gAl);
            CP16(d + 2 * TILEB, gBh);
            CP16(d + 3 * TILEB, gBl);
            CP_COMMIT(); CP_WAIT0();
        }
        __syncthreads();

        for (int s = 0; s < nst; ++s) {
            if (s + 1 < nst) {
                const int k0 = (s + 1) << 5;
                const uint32_t d = smb + ((s + 1) & 1) * STAGEB + stb;
                CP16(d,             gAh + k0);
                CP16(d + TILEB,     gAl + k0);
                CP16(d + 2 * TILEB, gBh + k0);
                CP16(d + 3 * TILEB, gBl + k0);
                CP_COMMIT();
            }
            const uint32_t sb = smb + (s & 1) * STAGEB;
#pragma unroll
            for (int kk = 0; kk < 2; ++kk) {
                const uint32_t kb = kk * 32;
                uint32_t ah[2][4], al[2][4], bh[4][2], bl[4][2];
#pragma unroll
                for (int mt = 0; mt < 2; ++mt) {
                    LDSM4(ah[mt], sb + aoff[mt] + kb);
                    LDSM4(al[mt], sb + TILEB + aoff[mt] + kb);
                }
#pragma unroll
                for (int p = 0; p < 2; ++p) {
                    uint32_t t4[4];
                    LDSM4(t4, sb + 2 * TILEB + boff[p] + kb);
                    bh[2 * p][0] = t4[0]; bh[2 * p][1] = t4[1];
                    bh[2 * p + 1][0] = t4[2]; bh[2 * p + 1][1] = t4[3];
                    LDSM4(t4, sb + 3 * TILEB + boff[p] + kb);
                    bl[2 * p][0] = t4[0]; bl[2 * p][1] = t4[1];
                    bl[2 * p + 1][0] = t4[2]; bl[2 * p + 1][1] = t4[3];
                }
#pragma unroll
                for (int mt = 0; mt < 2; ++mt)
#pragma unroll
                    for (int nt = 0; nt < 4; ++nt)
                        MMA_BF16(acc[mt][nt], ah[mt], bh[nt]);
#pragma unroll
                for (int mt = 0; mt < 2; ++mt)
#pragma unroll
                    for (int nt = 0; nt < 4; ++nt)
                        MMA_BF16(acc[mt][nt], ah[mt], bl[nt]);
#pragma unroll
                for (int mt = 0; mt < 2; ++mt)
#pragma unroll
                    for (int nt = 0; nt < 4; ++nt)
                        MMA_BF16(acc[mt][nt], al[mt], bh[nt]);
            }
            CP_WAIT0();
            __syncthreads();
        }

        // epilogue: q (*0.125) / k in [B,H,N,DH]
#pragma unroll
        for (int nt = 0; nt < 4; ++nt) {
            const int cc = n0 + nw * 32 + nt * 8 + ((lane & 3) << 1);
            const int sec = cc >> 10;          // 0 = q, 1 = k
            const int h = (cc & 1023) >> 6;
            const int d = cc & 63;
            __nv_bfloat16* hb = (sec == 0) ? qhi : khi;
            __nv_bfloat16* lb = (sec == 0) ? qlo : klo;
            const float sc = (sec == 0) ? 0.125f : 1.0f;
#pragma unroll
            for (int mt = 0; mt < 2; ++mt) {
                const int r0 = m0 + mw * 32 + mt * 16 + (lane >> 2);
                const int b = r0 >> 10;
                const int n = r0 & 1023;
                const size_t base = (((size_t)b * HH + h) * NN);
                store_hilo2(hb, lb, (base + n) * DHH + d,
                            acc[mt][nt][0] * sc, acc[mt][nt][1] * sc);
                store_hilo2(hb, lb, (base + n + 8) * DHH + d,
                            acc[mt][nt][2] * sc, acc[mt][nt][3] * sc);
            }
        }
    }
}

// ---------------------------------------------------------------------------
// tf32 GEMM core (shared by gemm_v and gemm_out). 128x128 tile, BK=32 floats.
// ---------------------------------------------------------------------------
#define TFSTR 36
#define TFTILEB (128 * TFSTR * 4)           // 18432
#define TFSTAGEB (2 * TFTILEB)              // 36864
#define TF_SMEM_BYTES (2 * TFSTAGEB)        // 73728

#define TF32_MAINLOOP(Aptr, Bptr, Kdim)                                       \
    float acc[2][4][4];                                                       \
    _Pragma("unroll")                                                         \
    for (int i = 0; i < 2; ++i)                                               \
        _Pragma("unroll")                                                     \
        for (int j = 0; j < 4; ++j)                                           \
            _Pragma("unroll")                                                 \
            for (int k = 0; k < 4; ++k) acc[i][j][k] = 0.f;                   \
    {                                                                         \
        const uint32_t d = smb + stb;                                         \
        CP16(d,      (Aptr)); CP16(d + 16,      (Aptr) + 4);                  \
        CP16(d + TFTILEB, (Bptr)); CP16(d + TFTILEB + 16, (Bptr) + 4);        \
        CP_COMMIT(); CP_WAIT0();                                              \
    }                                                                         \
    __syncthreads();                                                          \
    for (int s = 0; s < ((Kdim) >> 5); ++s) {                                 \
        if (s + 1 < ((Kdim) >> 5)) {                                          \
            const int k0 = (s + 1) << 5;                                      \
            const uint32_t d = smb + ((s + 1) & 1) * TFSTAGEB + stb;          \
            CP16(d,      (Aptr) + k0); CP16(d + 16,      (Aptr) + k0 + 4);    \
            CP16(d + TFTILEB, (Bptr) + k0);                                   \
            CP16(d + TFTILEB + 16, (Bptr) + k0 + 4);                          \
            CP_COMMIT();                                                      \
        }                                                                     \
        const uint32_t sb = smb + (s & 1) * TFSTAGEB;                         \
        _Pragma("unroll")                                                     \
        for (int kc = 0; kc < 4; ++kc) {                                      \
            const uint32_t kb = kc * 32;                                      \
            uint32_t af[2][4], bf[4][2];                                      \
            _Pragma("unroll")                                                 \
            for (int mt = 0; mt < 2; ++mt)                                    \
                LDSM4(af[mt], sb + aoff[mt] + kb);                            \
            _Pragma("unroll")                                                 \
            for (int p = 0; p < 2; ++p) {                                     \
                uint32_t t4[4];                                               \
                LDSM4(t4, sb + TFTILEB + boff[p] + kb);                       \
                bf[2 * p][0] = t4[0]; bf[2 * p][1] = t4[1];                   \
                bf[2 * p + 1][0] = t4[2]; bf[2 * p + 1][1] = t4[3];           \
            }                                                                 \
            _Pragma("unroll")                                                 \
            for (int mt = 0; mt < 2; ++mt)                                    \
                _Pragma("unroll")                                             \
                for (int nt = 0; nt < 4; ++nt)                                \
                    MMA_TF32(acc[mt][nt], af[mt], bf[nt]);                    \
        }                                                                     \
        CP_WAIT0();                                                           \
        __syncthreads();                                                      \
    }

#define TF32_SETUP()                                                          \
    extern __shared__ char smem[];                                            \
    const uint32_t smb = smem_u32(smem);                                      \
    const int tid = threadIdx.x;                                              \
    const int lane = tid & 31;                                                \
    const int wid = tid >> 5;                                                 \
    const int mw = wid >> 2;                                                  \
    const int nw = wid & 3;                                                   \
    const int grow = tid >> 2;                                                \
    const int gcolf = (tid & 3) << 3;                                         \
    const uint32_t stb = (uint32_t)(grow * TFSTR + gcolf) * 4;                \
    const int mat = lane >> 3;                                                \
    const int rr = lane & 7;                                                  \
    uint32_t aoff[2];                                                         \
    _Pragma("unroll")                                                         \
    for (int mt = 0; mt < 2; ++mt)                                            \
        aoff[mt] = (uint32_t)((mw * 32 + mt * 16 + ((mat & 1) << 3) + rr)     \
                              * TFSTR + ((mat >> 1) << 2)) * 4;               \
    uint32_t boff[2];                                                         \
    _Pragma("unroll")                                                         \
    for (int p = 0; p < 2; ++p)                                               \
        boff[p] = (uint32_t)((nw * 32 + p * 16 + ((mat >> 1) << 3) + rr)      \
                             * TFSTR + ((mat & 1) << 2)) * 4;

// V projection: V = xtf @ wvT^T; epilogue -> vT hi/lo [B,H,DH,N]
__global__ void __launch_bounds__(512, 1) gemm_v_tf32(
    const float* __restrict__ A, const float* __restrict__ Bt,
    __nv_bfloat16* __restrict__ vThi, __nv_bfloat16* __restrict__ vTlo)
{
    TF32_SETUP()
    const int NT = (MM >> 7) * (INNERC >> 7);   // 256

    for (int tile = blockIdx.x; tile < NT; tile += NSM) {
        const int m0 = (tile >> 3) << 7;
        const int n0 = (tile & 7) << 7;
        const float* gA = A  + (size_t)(m0 + grow) * DD + gcolf;
        const float* gB = Bt + (size_t)(n0 + grow) * DD + gcolf;

        TF32_MAINLOOP(gA, gB, DD)

#pragma unroll
        for (int nt = 0; nt < 4; ++nt) {
            const int cc = n0 + nw * 32 + nt * 8 + ((lane & 3) << 1);
            const int h = cc >> 6;
            const int d = cc & 63;
#pragma unroll
            for (int mt = 0; mt < 2; ++mt) {
                const int r0 = m0 + mw * 32 + mt * 16 + (lane >> 2);
                const int b = r0 >> 10;
                const int n = r0 & 1023;
                const size_t vb = ((size_t)b * HH + h) * DHH;
                store_hilo1(vThi, vTlo, (vb + d) * NN + n,         acc[mt][nt][0]);
                store_hilo1(vThi, vTlo, (vb + d + 1) * NN + n,     acc[mt][nt][1]);
                store_hilo1(vThi, vTlo, (vb + d) * NN + n + 8,     acc[mt][nt][2]);
                store_hilo1(vThi, vTlo, (vb + d + 1) * NN + n + 8, acc[mt][nt][3]);
            }
        }
    }
}

// out-projection: out = ao @ woT^T + bias
__global__ void __launch_bounds__(512, 1) gemm_out_tf32(
    const float* __restrict__ A, const float* __restrict__ Bt,
    const float* __restrict__ bias, float* __restrict__ C)
{
    TF32_SETUP()
    const int NT = (MM >> 7) * (INNERC >> 7);   // 256

    for (int tile = blockIdx.x; tile < NT; tile += NSM) {
        const int m0 = (tile >> 3) << 7;
        const int n0 = (tile & 7) << 7;
        const float* gA = A  + (size_t)(m0 + grow) * INNERC + gcolf;
        const float* gB = Bt + (size_t)(n0 + grow) * INNERC + gcolf;

        TF32_MAINLOOP(gA, gB, INNERC)

#pragma unroll
        for (int mt = 0; mt < 2; ++mt) {
            const int r0 = m0 + mw * 32 + mt * 16 + (lane >> 2);
#pragma unroll
            for (int nt = 0; nt < 4; ++nt) {
                const int cc = n0 + nw * 32 + nt * 8 + ((lane & 3) << 1);
                float2 bv = *(const float2*)(bias + cc);
                float2 v0 = make_float2(acc[mt][nt][0] + bv.x, acc[mt][nt][1] + bv.y);
                float2 v1 = make_float2(acc[mt][nt][2] + bv.x, acc[mt][nt][3] + bv.y);
                *(float2*)(C + (size_t)r0 * INNERC + cc) = v0;
                *(float2*)(C + (size_t)(r0 + 8) * INNERC + cc) = v1;
            }
        }
    }
}

// ---------------------------------------------------------------------------
// flash_tc: fused masked attention, 256 threads, persistent (proven).
// ---------------------------------------------------------------------------
#define FQSTR 72
#define FQTILE 18432                      // 128*72*2
#define FVSTR 136
#define FVTILE 17408                      // 64*136*2
#define F_MASK 0
#define F_QHI 4096
#define F_QLO (F_QHI + FQTILE)
#define F_K(st) (40960 + (st) * 2 * FQTILE)
#define F_V(st) (114688 + (st) * 2 * FVTILE)
#define FLASH_SMEM 184320

__global__ void __launch_bounds__(256, 1) flash_tc(
    const __nv_bfloat16* __restrict__ qhi, const __nv_bfloat16* __restrict__ qlo,
    const __nv_bfloat16* __restrict__ khi, const __nv_bfloat16* __restrict__ klo,
    const __nv_bfloat16* __restrict__ vThi, const __nv_bfloat16* __restrict__ vTlo,
    const float* __restrict__ mask, float* __restrict__ ao)
{
    extern __shared__ char smem[];
    const uint32_t smb = smem_u32(smem);
    const int tid = threadIdx.x;
    const int lane = tid & 31;
    const int wid = tid >> 5;
    const int rw = wid * 16;
    const int rloc = lane >> 2;

    const uint32_t bkbase = (uint32_t)(((lane & 7) + ((lane >> 4) << 3)) * FQSTR
                                       + (((lane >> 3) & 1) << 3)) * 2;
    const uint32_t bvbase = (uint32_t)(((lane & 7) + ((lane >> 4) << 3)) * FVSTR
                                       + (((lane >> 3) & 1) << 3)) * 2;
    const uint32_t aQ = (uint32_t)((rw + (lane & 15)) * FQSTR + ((lane >> 4) << 3)) * 2;
    const float* smask = (const float*)smem;

    for (int tile = blockIdx.x; tile < 512; tile += NSM) {
        const int bh = tile >> 3;
        const int i0 = (tile & 7) << 7;
        const int b = bh >> 4;
        const int h = bh & 15;
        const size_t hb = (size_t)bh * NN * DHH;
        const __nv_bfloat16* kH = khi + hb;
        const __nv_bfloat16* kL = klo + hb;
        const __nv_bfloat16* vH = vThi + (size_t)bh * DHH * NN;
        const __nv_bfloat16* vL = vTlo + (size_t)bh * DHH * NN;

        CP16(smb + F_MASK + tid * 16, mask + b * NN + tid * 4);
#pragma unroll
        for (int t = 0; t < 4; ++t) {
            const int idx = tid + t * 256;
            const int row = idx >> 3;
            const int col = (idx & 7) << 3;
            const uint32_t so = (uint32_t)(row * FQSTR + col) * 2;
            CP16(smb + F_QHI + so, qhi + hb + (size_t)(i0 + row) * DHH + col);
            CP16(smb + F_QLO + so, qlo + hb + (size_t)(i0 + row) * DHH + col);
            CP16(smb + F_K(0) + so,          kH + (size_t)row * DHH + col);
            CP16(smb + F_K(0) + FQTILE + so, kL + (size_t)row * DHH + col);
        }
#pragma unroll
        for (int t = 0; t < 4; ++t) {
            const int idx = tid + t * 256;
            const int vr = idx >> 4;
            const int vc = (idx & 15) << 3;
            const uint32_t so = (uint32_t)(vr * FVSTR + vc) * 2;
            CP16(smb + F_V(0) + so,          vH + (size_t)vr * NN + vc);
            CP16(smb + F_V(0) + FVTILE + so, vL + (size_t)vr * NN + vc);
        }
        CP_COMMIT(); CP_WAIT0();
        __syncthreads();

        uint32_t qfh[4][4], qfl[4][4];
#pragma unroll
        for (int kk = 0; kk < 4; ++kk) {
            LDSM4(qfh[kk], smb + F_QHI + aQ + kk * 32);
            LDSM4(qfl[kk], smb + F_QLO + aQ + kk * 32);
        }

        const float mi0 = mask[b * NN + i0 + rw + rloc];
        const float mi1 = mask[b * NN + i0 + rw + rloc + 8];
        const bool rv0 = (mi0 != 0.f);
        const bool rv1 = (mi1 != 0.f);
        float m0 = -1e30f, m1 = -1e30f, l0 = 0.f, l1 = 0.f;
        float oacc[8][4];
#pragma unroll
        for (int i = 0; i < 8; ++i)
#pragma unroll
            for (int j = 0; j < 4; ++j) oacc[i][j] = 0.f;

        for (int kt = 0; kt < 8; ++kt) {
            if (kt + 1 < 8) {
                const int st = (kt + 1) & 1;
                const int j0 = (kt + 1) * 128;
#pragma unroll
                for (int t = 0; t < 4; ++t) {
                    const int idx = tid + t * 256;
                    const int row = idx >> 3;
                    const int col = (idx & 7) << 3;
                    const uint32_t so = (uint32_t)(row * FQSTR + col) * 2;
                    CP16(smb + F_K(st) + so,          kH + (size_t)(j0 + row) * DHH + col);
                    CP16(smb + F_K(st) + FQTILE + so, kL + (size_t)(j0 + row) * DHH + col);
                }
#pragma unroll
                for (int t = 0; t < 4; ++t) {
                    const int idx = tid + t * 256;
                    const int vr = idx >> 4;
                    const int vc = (idx & 15) << 3;
                    const uint32_t so = (uint32_t)(vr * FVSTR + vc) * 2;
                    CP16(smb + F_V(st) + so,          vH + (size_t)vr * NN + j0 + vc);
                    CP16(smb + F_V(st) + FVTILE + so, vL + (size_t)vr * NN + j0 + vc);
                }
                CP_COMMIT();
            }

            const uint32_t kbh = smb + F_K(kt & 1);
            const uint32_t kbl = kbh + FQTILE;
            const uint32_t vbh = smb + F_V(kt & 1);
            const uint32_t vbl = vbh + FVTILE;

            float sacc[16][4];
#pragma unroll
            for (int i = 0; i < 16; ++i)
#pragma unroll
                for (int j = 0; j < 4; ++j) sacc[i][j] = 0.f;
#pragma unroll
            for (int kk = 0; kk < 4; ++kk) {
                const uint32_t kb = kk * 32;
#pragma unroll
                for (int p = 0; p < 8; ++p) {
                    uint32_t tbh[4], tbl[4];
                    LDSM4(tbh, kbh + bkbase + p * 2304 + kb);
                    LDSM4(tbl, kbl + bkbase + p * 2304 + kb);
                    MMA_BF16(sacc[2 * p],     qfh[kk], tbh);
                    MMA_BF16(sacc[2 * p + 1], qfh[kk], tbh + 2);
                    MMA_BF16(sacc[2 * p],     qfh[kk], tbl);
                    MMA_BF16(sacc[2 * p + 1], qfh[kk], tbl + 2);
                    MMA_BF16(sacc[2 * p],     qfl[kk], tbh);
                    MMA_BF16(sacc[2 * p + 1], qfl[kk], tbh + 2);
                }
            }

            const int kt128 = kt * 128;
            float tmax0 = -1e30f, tmax1 = -1e30f;
#pragma unroll
            for (int nt = 0; nt < 16; ++nt) {
                const float2 mv = *(const float2*)(smask + kt128 + nt * 8 + ((lane & 3) << 1));
                const bool g0 = (mv.x != 0.f);
                const bool g1 = (mv.y != 0.f);
                float s0 = (rv0 && g0) ? sacc[nt][0] : -1e30f;
                float s1 = (rv0 && g1) ? sacc[nt][1] : -1e30f;
                float s2 = (rv1 && g0) ? sacc[nt][2] : -1e30f;
                float s3 = (rv1 && g1) ? sacc[nt][3] : -1e30f;
                sacc[nt][0] = s0; sacc[nt][1] = s1; sacc[nt][2] = s2; sacc[nt][3] = s3;
                tmax0 = fmaxf(tmax0, fmaxf(s0, s1));
                tmax1 = fmaxf(tmax1, fmaxf(s2, s3));
            }
            tmax0 = fmaxf(tmax0, __shfl_xor_sync(0xffffffffu, tmax0, 1));
            tmax0 = fmaxf(tmax0, __shfl_xor_sync(0xffffffffu, tmax0, 2));
            tmax1 = fmaxf(tmax1, __shfl_xor_sync(0xffffffffu, tmax1, 1));
            tmax1 = fmaxf(tmax1, __shfl_xor_sync(0xffffffffu, tmax1, 2));
            const float mn0 = fmaxf(m0, tmax0);
            const float mn1 = fmaxf(m1, tmax1);
            const float sc0 = __expf(m0 - mn0);
            const float sc1 = __expf(m1 - mn1);
            m0 = mn0; m1 = mn1;

            float ls0 = 0.f, ls1 = 0.f;
#pragma unroll
            for (int nt = 0; nt < 16; ++nt) {
                float e0 = (sacc[nt][0] > -1e29f) ? __expf(sacc[nt][0] - mn0) : 0.f;
                float e1 = (sacc[nt][1] > -1e29f) ? __expf(sacc[nt][1] - mn0) : 0.f;
                float e2 = (sacc[nt][2] > -1e29f) ? __expf(sacc[nt][2] - mn1) : 0.f;
                float e3 = (sacc[nt][3] > -1e29f) ? __expf(sacc[nt][3] - mn1) : 0.f;
                sacc[nt][0] = e0; sacc[nt][1] = e1; sacc[nt][2] = e2; sacc[nt][3] = e3;
                ls0 += e0 + e1; ls1 += e2 + e3;
            }
            ls0 += __shfl_xor_sync(0xffffffffu, ls0, 1);
            ls0 += __shfl_xor_sync(0xffffffffu, ls0, 2);
            ls1 += __shfl_xor_sync(0xffffffffu, ls1, 1);
            ls1 += __shfl_xor_sync(0xffffffffu, ls1, 2);
            l0 = l0 * sc0 + ls0;
            l1 = l1 * sc1 + ls1;
#pragma unroll
            for (int no = 0; no < 8; ++no) {
                oacc[no][0] *= sc0; oacc[no][1] *= sc0;
                oacc[no][2] *= sc1; oacc[no][3] *= sc1;
            }

#pragma unroll
            for (int kc = 0; kc < 8; ++kc) {
                uint32_t pah[4], pal[4];
                cvt_hilo(sacc[2 * kc][0],     sacc[2 * kc][1],     pah[0], pal[0]);
                cvt_hilo(sacc[2 * kc][2],     sacc[2 * kc][3],     pah[1], pal[1]);
                cvt_hilo(sacc[2 * kc + 1][0], sacc[2 * kc + 1][1], pah[2], pal[2]);
                cvt_hilo(sacc[2 * kc + 1][2], sacc[2 * kc + 1][3], pah[3], pal[3]);
#pragma unroll
                for (int dv = 0; dv < 4; ++dv) {
                    uint32_t vb[4], vl[4];
                    LDSM4(vb, vbh + bvbase + dv * 4352 + kc * 32);
                    LDSM4(vl, vbl + bvbase + dv * 4352 + kc * 32);
                    MMA_BF16(oacc[2 * dv],     pah, vb);
                    MMA_BF16(oacc[2 * dv + 1], pah, vb + 2);
                    MMA_BF16(oacc[2 * dv],     pah, vl);
                    MMA_BF16(oacc[2 * dv + 1], pah, vl + 2);
                    MMA_BF16(oacc[2 * dv],     pal, vb);
                    MMA_BF16(oacc[2 * dv + 1], pal, vb + 2);
                }
            }
            CP_WAIT0();
            __syncthreads();
        }

        const float inv0 = (l0 > 0.f) ? 1.f / l0 : 0.f;
        const float inv1 = (l1 > 0.f) ? 1.f / l1 : 0.f;
        const int r0g = i0 + rw + rloc;
#pragma unroll
        for (int no = 0; no < 8; ++no) {
            const size_t c = (size_t)h * 64 + no * 8 + ((lane & 3) << 1);
            ao[((size_t)b * NN + r0g) * INNERC + c]         = tf32rna(oacc[no][0] * inv0);
            ao[((size_t)b * NN + r0g) * INNERC + c + 1]     = tf32rna(oacc[no][1] * inv0);
            ao[((size_t)b * NN + r0g + 8) * INNERC + c]     = tf32rna(oacc[no][2] * inv1);
            ao[((size_t)b * NN + r0g + 8) * INNERC + c + 1] = tf32rna(oacc[no][3] * inv1);
        }
    }
}

// ---------------------------------------------------------------------------
extern "C" void kernel_launch(void* const* d_in, const int* in_sizes, int n_in,
                              void* d_out, int out_size)
{
    const float* x      = (const float*)d_in[0];
    const float* mask   = (const float*)d_in[1];
    const float* w_qkv  = (const float*)d_in[2];
    const float* w_out  = (const float*)d_in[3];
    const float* b_out  = (const float*)d_in[4];
    float* out = (float*)d_out;

    __nv_bfloat16 *xhi, *xlo, *wqhi, *wqlo;
    __nv_bfloat16 *qhi, *qlo, *khi, *klo, *vThi, *vTlo;
    float *xtf, *wvT, *woT, *ao;
    cudaGetSymbolAddress((void**)&xhi, g_xhi);
    cudaGetSymbolAddress((void**)&xlo, g_xlo);
    cudaGetSymbolAddress((void**)&xtf, g_xtf);
    cudaGetSymbolAddress((void**)&wqhi, g_wqkvThi);
    cudaGetSymbolAddress((void**)&wqlo, g_wqkvTlo);
    cudaGetSymbolAddress((void**)&wvT, g_wvT);
    cudaGetSymbolAddress((void**)&woT, g_woT);
    cudaGetSymbolAddress((void**)&ao, g_ao);
    cudaGetSymbolAddress((void**)&qhi, g_qhi);
    cudaGetSymbolAddress((void**)&qlo, g_qlo);
    cudaGetSymbolAddress((void**)&khi, g_khi);
    cudaGetSymbolAddress((void**)&klo, g_klo);
    cudaGetSymbolAddress((void**)&vThi, g_vThi);
    cudaGetSymbolAddress((void**)&vTlo, g_vTlo);

    cudaFuncSetAttribute(gemm_qk, cudaFuncAttributeMaxDynamicSharedMemorySize,
                         GEMM_SMEM_BYTES);
    cudaFuncSetAttribute(gemm_v_tf32, cudaFuncAttributeMaxDynamicSharedMemorySize,
                         TF_SMEM_BYTES);
    cudaFuncSetAttribute(gemm_out_tf32, cudaFuncAttributeMaxDynamicSharedMemorySize,
                         TF_SMEM_BYTES);
    cudaFuncSetAttribute(flash_tc, cudaFuncAttributeMaxDynamicSharedMemorySize,
                         FLASH_SMEM);

    // 0) prep
    split_kernel<<<(MM * DD / 4 + 255) / 256, 256>>>(x, xhi, xlo, xtf, MM * DD / 4);
    splitT_kernel<<<dim3(2 * INNERC / 32, DD / 32), dim3(32, 8)>>>(
        w_qkv, wqhi, wqlo, DD, QKVC);                       // q,k columns 0..2047
    transT_rna<<<dim3(INNERC / 32, DD / 32), dim3(32, 8)>>>(
        w_qkv + 2 * INNERC, wvT, DD, QKVC);                 // v columns 2048..3071
    transT_rna<<<dim3(INNERC / 32, INNERC / 32), dim3(32, 8)>>>(
        w_out, woT, INNERC, INNERC);
    // 1) q/k projection (persistent bf16-3) and v projection (tf32)
    gemm_qk<<<NSM, 512, GEMM_SMEM_BYTES>>>(
        xhi, xlo, wqhi, wqlo, qhi, qlo, khi, klo);
    gemm_v_tf32<<<NSM, 512, TF_SMEM_BYTES>>>(xtf, wvT, vThi, vTlo);
    // 2) fused masked flash attention (persistent, 256 thr) -> ao fp32(tf32)
    flash_tc<<<NSM, 256, FLASH_SMEM>>>(
        qhi, qlo, khi, klo, vThi, vTlo, mask, ao);
    // 3) out projection (persistent tf32 single-product)
    gemm_out_tf32<<<NSM, 512, TF_SMEM_BYTES>>>(ao, woT, b_out, out);
}